// round 1
// baseline (speedup 1.0000x reference)
#include <cuda_runtime.h>
#include <math.h>

#define N_NODES 50000
#define N_EDGES 640000
#define HDIM 128
#define NH (N_NODES * HDIM)

// ---------------- scratch (static device globals; no runtime allocation) ----
__device__ float g_deg[N_NODES];     // 1 + in-degree
__device__ float g_z[3 * NH];        // pre-activation gates i, c, o
__device__ float g_Hs[NH];           // LSTM hidden state
__device__ float g_hh[NH];           // dg[n] * (Hs @ gcn_w)[n]
__device__ float g_acc[NH];          // edge-scatter accumulator

// ---------------- init: zero acc, deg = 1 (self loop) -----------------------
__global__ void init_kernel() {
    int i = blockIdx.x * blockDim.x + threadIdx.x;
    if (i < NH) g_acc[i] = 0.0f;
    if (i < N_NODES) g_deg[i] = 1.0f;
}

// ---------------- degree histogram over dst ---------------------------------
__global__ void deg_kernel(const int* __restrict__ dst) {
    int e = blockIdx.x * blockDim.x + threadIdx.x;
    if (e < N_EDGES) atomicAdd(&g_deg[dst[e]], 1.0f);
}

// ---------------- fp32 SGEMM: C[M,128] = A[M,128] @ B[128,128] --------------
// BM=128, BN=128, BK=16, 256 threads, 8x8 microtile.
// mode==1: scale each output row by rsqrt(g_deg[row]) (produces hh).
__global__ __launch_bounds__(256) void sgemm128(
    const float* __restrict__ A, const float* __restrict__ B,
    float* __restrict__ C, int M, int mode)
{
    __shared__ float As[16][128];  // transposed: As[k][m]
    __shared__ float Bs[16][128];

    int tid = threadIdx.x;
    int row0 = blockIdx.x * 128;
    int tx = tid & 15, ty = tid >> 4;

    float acc[8][8];
#pragma unroll
    for (int i = 0; i < 8; i++)
#pragma unroll
        for (int j = 0; j < 8; j++) acc[i][j] = 0.0f;

    for (int k0 = 0; k0 < 128; k0 += 16) {
        // A tile: 128 rows x 16 cols = 512 float4, 2 per thread (transposed store)
#pragma unroll
        for (int i = 0; i < 2; i++) {
            int idx = tid * 2 + i;
            int ar = idx >> 2;
            int ac = (idx & 3) * 4;
            float4 v = make_float4(0.f, 0.f, 0.f, 0.f);
            int grow = row0 + ar;
            if (grow < M) v = *(const float4*)(A + grow * 128 + k0 + ac);
            As[ac + 0][ar] = v.x;
            As[ac + 1][ar] = v.y;
            As[ac + 2][ar] = v.z;
            As[ac + 3][ar] = v.w;
        }
        // B tile: 16 rows x 128 cols = 512 float4, 2 per thread
#pragma unroll
        for (int i = 0; i < 2; i++) {
            int idx = tid * 2 + i;
            int br = idx >> 5;
            int bc = (idx & 31) * 4;
            *(float4*)(&Bs[br][bc]) = *(const float4*)(B + (k0 + br) * 128 + bc);
        }
        __syncthreads();

#pragma unroll
        for (int kk = 0; kk < 16; kk++) {
            float a[8], bv[8];
            *(float4*)(a)     = *(const float4*)(&As[kk][ty * 8]);
            *(float4*)(a + 4) = *(const float4*)(&As[kk][ty * 8 + 4]);
            *(float4*)(bv)     = *(const float4*)(&Bs[kk][tx * 8]);
            *(float4*)(bv + 4) = *(const float4*)(&Bs[kk][tx * 8 + 4]);
#pragma unroll
            for (int i = 0; i < 8; i++)
#pragma unroll
                for (int j = 0; j < 8; j++)
                    acc[i][j] = fmaf(a[i], bv[j], acc[i][j]);
        }
        __syncthreads();
    }

#pragma unroll
    for (int i = 0; i < 8; i++) {
        int grow = row0 + ty * 8 + i;
        if (grow >= M) break;
        float s = 1.0f;
        if (mode) s = rsqrtf(g_deg[grow]);
        float4 v0 = make_float4(acc[i][0] * s, acc[i][1] * s, acc[i][2] * s, acc[i][3] * s);
        float4 v1 = make_float4(acc[i][4] * s, acc[i][5] * s, acc[i][6] * s, acc[i][7] * s);
        *(float4*)(C + grow * 128 + tx * 8)     = v0;
        *(float4*)(C + grow * 128 + tx * 8 + 4) = v1;
    }
}

// ---------------- LSTM elementwise (Hs=C=0 initial state) -------------------
// I = sig(zi + tb0 + b0); T = tanh(zc + tb2 + b2); Cs = I*T;
// O = sig(zo + tb3 + b3 + wc2*Cs); Hs = O*tanh(Cs)
__global__ void lstm_elt(const float* __restrict__ theta_b,
                         const float* __restrict__ b,
                         const float* __restrict__ w_c)
{
    int idx = blockIdx.x * blockDim.x + threadIdx.x;
    if (idx >= NH) return;
    int c = idx & 127;
    float zi = g_z[idx]          + theta_b[c]       + b[c];
    float zc = g_z[idx + NH]     + theta_b[256 + c] + b[256 + c];
    float zo = g_z[idx + 2 * NH] + theta_b[384 + c] + b[384 + c];
    float I = 1.0f / (1.0f + expf(-zi));
    float T = tanhf(zc);
    float Cs = I * T;
    float O = 1.0f / (1.0f + expf(-(zo + w_c[256 + c] * Cs)));
    g_Hs[idx] = O * tanhf(Cs);
}

// ---------------- edge scatter: acc[dst] += hh[src] (128 floats/edge) -------
// One warp per edge; each lane handles one float4 with a vector reduction atomic.
__global__ void scatter_kernel(const int* __restrict__ src,
                               const int* __restrict__ dst)
{
    int gw = (blockIdx.x * blockDim.x + threadIdx.x) >> 5;
    int lane = threadIdx.x & 31;
    if (gw >= N_EDGES) return;
    int s = src[gw];
    int d = dst[gw];
    float4 v = __ldg((const float4*)g_hh + s * 32 + lane);
    float* ap = g_acc + d * 128 + lane * 4;
    asm volatile("red.global.add.v4.f32 [%0], {%1,%2,%3,%4};"
                 :: "l"(ap), "f"(v.x), "f"(v.y), "f"(v.z), "f"(v.w)
                 : "memory");
}

// ---------------- finalize: g = dg*(acc+hh)+gcn_b; relu; BN; dot lin_w ------
__global__ void finalize_kernel(const float* __restrict__ gcn_b,
                                const float* __restrict__ gamma,
                                const float* __restrict__ beta,
                                const float* __restrict__ mean,
                                const float* __restrict__ var,
                                const float* __restrict__ lin_w,
                                const float* __restrict__ lin_b,
                                float* __restrict__ out)
{
    int node = (blockIdx.x * blockDim.x + threadIdx.x) >> 5;
    int lane = threadIdx.x & 31;
    if (node >= N_NODES) return;
    float dg = rsqrtf(g_deg[node]);

    float4 a  = *((const float4*)g_acc + node * 32 + lane);
    float4 h  = *((const float4*)g_hh  + node * 32 + lane);
    float4 gb = ((const float4*)gcn_b)[lane];
    float4 gm = ((const float4*)gamma)[lane];
    float4 bt = ((const float4*)beta)[lane];
    float4 mn = ((const float4*)mean)[lane];
    float4 vr = ((const float4*)var)[lane];
    float4 lw = ((const float4*)lin_w)[lane];

    float sum = 0.0f;
    {
        float gx = dg * (a.x + h.x) + gb.x; gx = fmaxf(gx, 0.0f);
        gx = gm.x * (gx - mn.x) * rsqrtf(vr.x + 1e-5f) + bt.x; sum += gx * lw.x;
    }
    {
        float gx = dg * (a.y + h.y) + gb.y; gx = fmaxf(gx, 0.0f);
        gx = gm.y * (gx - mn.y) * rsqrtf(vr.y + 1e-5f) + bt.y; sum += gx * lw.y;
    }
    {
        float gx = dg * (a.z + h.z) + gb.z; gx = fmaxf(gx, 0.0f);
        gx = gm.z * (gx - mn.z) * rsqrtf(vr.z + 1e-5f) + bt.z; sum += gx * lw.z;
    }
    {
        float gx = dg * (a.w + h.w) + gb.w; gx = fmaxf(gx, 0.0f);
        gx = gm.w * (gx - mn.w) * rsqrtf(vr.w + 1e-5f) + bt.w; sum += gx * lw.w;
    }
#pragma unroll
    for (int o = 16; o > 0; o >>= 1)
        sum += __shfl_down_sync(0xffffffffu, sum, o);
    if (lane == 0) out[node] = sum + lin_b[0];
}

// ---------------- launch ----------------------------------------------------
extern "C" void kernel_launch(void* const* d_in, const int* in_sizes, int n_in,
                              void* d_out, int out_size)
{
    const float* x        = (const float*)d_in[0];
    const int*   ei       = (const int*)  d_in[1];
    // d_in[2] = edge_weight  (dead: only feeds ChebConv on a zero input)
    const float* W_x      = (const float*)d_in[3];
    const float* w_c      = (const float*)d_in[4];
    const float* b        = (const float*)d_in[5];
    // d_in[6] = theta        (dead)
    const float* theta_b  = (const float*)d_in[7];
    const float* gcn_w    = (const float*)d_in[8];
    const float* gcn_b    = (const float*)d_in[9];
    const float* bn_gamma = (const float*)d_in[10];
    const float* bn_beta  = (const float*)d_in[11];
    const float* bn_mean  = (const float*)d_in[12];
    const float* bn_var   = (const float*)d_in[13];
    const float* lin_w    = (const float*)d_in[14];
    const float* lin_b    = (const float*)d_in[15];
    float* out = (float*)d_out;

    const int* src = ei;            // edge_index[0]
    const int* dst = ei + N_EDGES;  // edge_index[1]

    float *zp, *hsp, *hhp;
    cudaGetSymbolAddress((void**)&zp,  g_z);
    cudaGetSymbolAddress((void**)&hsp, g_Hs);
    cudaGetSymbolAddress((void**)&hhp, g_hh);

    init_kernel<<<(NH + 255) / 256, 256>>>();
    deg_kernel<<<(N_EDGES + 255) / 256, 256>>>(dst);

    int mb = (N_NODES + 127) / 128;
    // gates: i -> W_x[0], c -> W_x[2], o -> W_x[3]   (f is dead: Cs0 = 0)
    sgemm128<<<mb, 256>>>(x, W_x + 0 * 128 * 128, zp,           N_NODES, 0);
    sgemm128<<<mb, 256>>>(x, W_x + 2 * 128 * 128, zp + NH,      N_NODES, 0);
    sgemm128<<<mb, 256>>>(x, W_x + 3 * 128 * 128, zp + 2 * NH,  N_NODES, 0);

    lstm_elt<<<(NH + 255) / 256, 256>>>(theta_b, b, w_c);

    // hh = dg * (Hs @ gcn_w)
    sgemm128<<<mb, 256>>>(hsp, gcn_w, hhp, N_NODES, 1);

    scatter_kernel<<<(N_EDGES * 32 + 255) / 256, 256>>>(src, dst);

    finalize_kernel<<<(N_NODES * 32 + 255) / 256, 256>>>(
        gcn_b, bn_gamma, bn_beta, bn_mean, bn_var, lin_w, lin_b, out);
}

// round 3
// speedup vs baseline: 1.9124x; 1.9124x over previous
#include <cuda_runtime.h>
#include <cstdint>
#include <math.h>

#define N_NODES 50000
#define N_EDGES 640000
#define NH (N_NODES * 128)

// ---------------- scratch (static device globals) ---------------------------
__device__ float g_Hs[NH];            // LSTM hidden state
__device__ float g_hh[NH];            // dg[n] * (Hs @ gcn_w)[n]
__device__ int   g_indeg[N_NODES];
__device__ int   g_off[N_NODES + 1];
__device__ int   g_cursor[N_NODES];
__device__ int   g_csr[N_EDGES];
// fused per-channel constants
__device__ float g_cb0[128], g_cb1[128], g_cb2[128], g_wc2[128];
__device__ float g_fa[128];
__device__ float g_fc;

// ---------------- helpers ----------------------------------------------------
__device__ __forceinline__ float tanhfast(float x) {
    float r; asm("tanh.approx.f32 %0, %1;" : "=f"(r) : "f"(x)); return r;
}
__device__ __forceinline__ float sigfast(float x) {
    return 0.5f * tanhfast(0.5f * x) + 0.5f;
}
__device__ __forceinline__ uint32_t to_tf32(float x) {
    uint32_t u; asm("cvt.rna.tf32.f32 %0, %1;" : "=r"(u) : "f"(x)); return u;
}
__device__ __forceinline__ void mma_tf32(float* d, const uint32_t* a, uint32_t b0, uint32_t b1) {
    asm volatile(
        "mma.sync.aligned.m16n8k8.row.col.f32.tf32.tf32.f32 "
        "{%0,%1,%2,%3}, {%4,%5,%6,%7}, {%8,%9}, {%0,%1,%2,%3};"
        : "+f"(d[0]), "+f"(d[1]), "+f"(d[2]), "+f"(d[3])
        : "r"(a[0]), "r"(a[1]), "r"(a[2]), "r"(a[3]), "r"(b0), "r"(b1));
}

// ---------------- small kernels ----------------------------------------------
__global__ void prep_kernel(const float* __restrict__ theta_b, const float* __restrict__ b,
                            const float* __restrict__ w_c,
                            const float* __restrict__ gamma, const float* __restrict__ beta,
                            const float* __restrict__ mean, const float* __restrict__ var,
                            const float* __restrict__ lin_w, const float* __restrict__ lin_b) {
    int ch = threadIdx.x;  // 128
    g_cb0[ch] = theta_b[ch] + b[ch];                 // gate i
    g_cb1[ch] = theta_b[256 + ch] + b[256 + ch];     // gate c
    g_cb2[ch] = theta_b[384 + ch] + b[384 + ch];     // gate o
    g_wc2[ch] = w_c[256 + ch];
    float sc = gamma[ch] * rsqrtf(var[ch] + 1e-5f);
    g_fa[ch] = sc * lin_w[ch];
    __shared__ float red[128];
    red[ch] = (beta[ch] - mean[ch] * sc) * lin_w[ch];
    __syncthreads();
    for (int o = 64; o > 0; o >>= 1) { if (ch < o) red[ch] += red[ch + o]; __syncthreads(); }
    if (ch == 0) g_fc = red[0] + lin_b[0];
}

__global__ void init_kernel() {
    int i = blockIdx.x * blockDim.x + threadIdx.x;
    if (i < N_NODES) { g_indeg[i] = 0; g_cursor[i] = 0; }
}
__global__ void count_kernel(const int* __restrict__ dst) {
    int e = blockIdx.x * blockDim.x + threadIdx.x;
    if (e < N_EDGES) atomicAdd(&g_indeg[dst[e]], 1);
}
__global__ __launch_bounds__(1024) void prefix_kernel() {
    __shared__ int s[1024];
    const int CH = (N_NODES + 1023) / 1024;  // 49
    int t = threadIdx.x, base = t * CH, sum = 0;
#pragma unroll
    for (int i = 0; i < CH; i++) { int n = base + i; if (n < N_NODES) sum += g_indeg[n]; }
    s[t] = sum; __syncthreads();
    for (int off = 1; off < 1024; off <<= 1) {
        int v = (t >= off) ? s[t - off] : 0; __syncthreads();
        s[t] += v; __syncthreads();
    }
    int run = (t == 0) ? 0 : s[t - 1];
#pragma unroll
    for (int i = 0; i < CH; i++) { int n = base + i; if (n < N_NODES) { g_off[n] = run; run += g_indeg[n]; } }
    if (t == 1023) g_off[N_NODES] = run;
}
__global__ void fill_kernel(const int* __restrict__ src, const int* __restrict__ dst) {
    int e = blockIdx.x * blockDim.x + threadIdx.x;
    if (e >= N_EDGES) return;
    int d = dst[e];
    g_csr[g_off[d] + atomicAdd(&g_cursor[d], 1)] = src[e];
}

// ============================================================================
// tf32 mma.sync GEMM: out[128-tile,128] = A @ B  (B is [K=128][N=128] row-major)
// NG=3: gates i,c,o + fused LSTM -> Hs.   NG=1: fused rsqrt(1+indeg) scale -> hh.
// 256 thr, 8 warps 2(m)x4(n), warp tile 64x32, K chunks of 64.
// smem: A [128][68] tf32 bits, per-gate B [64][136] tf32 bits (8704 u32 each).
// ============================================================================
template <int NG>
__global__ __launch_bounds__(256, 1) void gemm_tc(
    const float* __restrict__ A,
    const float* __restrict__ B0, const float* __restrict__ B1, const float* __restrict__ B2,
    float* __restrict__ out, int M)
{
    extern __shared__ uint32_t sm[];  // [0,8704): A ; [8704*(1+g), +8704): B_g
    const int tid = threadIdx.x, lane = tid & 31;
    const int wid = tid >> 5, wm = wid >> 2, wn = wid & 3;
    const int q = lane >> 2, r = lane & 3;
    const int rowblk = blockIdx.x * 128;
    const float* Bp[3] = { B0, B1, B2 };

    float C[NG][4][4][4];
#pragma unroll
    for (int g = 0; g < NG; g++)
#pragma unroll
        for (int i = 0; i < 4; i++)
#pragma unroll
            for (int j = 0; j < 4; j++)
#pragma unroll
                for (int k = 0; k < 4; k++) C[g][i][j][k] = 0.0f;

#pragma unroll
    for (int chunk = 0; chunk < 2; chunk++) {
        const int k0 = chunk * 64;
        if (chunk) __syncthreads();
        // ---- load A chunk: 128 rows x 64 k, pitch 68 ----
#pragma unroll
        for (int t = 0; t < 8; t++) {
            int i = tid + t * 256;            // 0..2047
            int row = i >> 4, j = i & 15;
            int gr = rowblk + row;
            float4 v = make_float4(0.f, 0.f, 0.f, 0.f);
            if (gr < M) v = *(const float4*)(A + (size_t)gr * 128 + k0 + j * 4);
            uint32_t* p = &sm[row * 68 + j * 4];
            p[0] = to_tf32(v.x); p[1] = to_tf32(v.y); p[2] = to_tf32(v.z); p[3] = to_tf32(v.w);
        }
        // ---- load B chunk(s): 64 k x 128 n, pitch 136 ----
#pragma unroll
        for (int g = 0; g < NG; g++) {
            const float* Bg = Bp[g];
            uint32_t* bs = sm + 8704 * (1 + g);
#pragma unroll
            for (int t = 0; t < 8; t++) {
                int i = tid + t * 256;
                int row = i >> 5, j = i & 31;
                float4 v = *(const float4*)(Bg + (size_t)(k0 + row) * 128 + j * 4);
                uint32_t* p = &bs[row * 136 + j * 4];
                p[0] = to_tf32(v.x); p[1] = to_tf32(v.y); p[2] = to_tf32(v.z); p[3] = to_tf32(v.w);
            }
        }
        __syncthreads();

        // ---- compute ----
#pragma unroll
        for (int ks = 0; ks < 8; ks++) {
            const int kb = ks * 8;
            uint32_t a[4][4];
#pragma unroll
            for (int ma = 0; ma < 4; ma++) {
                int m = wm * 64 + ma * 16 + q;
                const uint32_t* ap = &sm[m * 68 + kb + r];
                a[ma][0] = ap[0];
                a[ma][2] = ap[4];
                a[ma][1] = ap[8 * 68];
                a[ma][3] = ap[8 * 68 + 4];
            }
#pragma unroll
            for (int g = 0; g < NG; g++) {
                const uint32_t* bs = sm + 8704 * (1 + g);
#pragma unroll
                for (int na = 0; na < 4; na++) {
                    int n = wn * 32 + na * 8 + q;
                    const uint32_t* bp = &bs[(kb + r) * 136 + n];
                    uint32_t b0 = bp[0], b1 = bp[4 * 136];
#pragma unroll
                    for (int ma = 0; ma < 4; ma++) mma_tf32(C[g][ma][na], a[ma], b0, b1);
                }
            }
        }
    }

    // ---- epilogue ----
#pragma unroll
    for (int ma = 0; ma < 4; ma++) {
#pragma unroll
        for (int half = 0; half < 2; half++) {
            int row = rowblk + wm * 64 + ma * 16 + q + half * 8;
            if (row >= M) continue;
            if (NG == 3) {
#pragma unroll
                for (int na = 0; na < 4; na++) {
                    int ch = wn * 32 + na * 8 + 2 * r;
                    float h2[2];
#pragma unroll
                    for (int e = 0; e < 2; e++) {
                        int c = ch + e;
                        float zi = C[0][ma][na][half * 2 + e] + g_cb0[c];
                        float zc = C[NG > 1 ? 1 : 0][ma][na][half * 2 + e] + g_cb1[c];
                        float zo = C[NG > 1 ? 2 : 0][ma][na][half * 2 + e] + g_cb2[c];
                        float I = sigfast(zi);
                        float T = tanhfast(zc);
                        float Cs = I * T;
                        float O = sigfast(zo + g_wc2[c] * Cs);
                        h2[e] = O * tanhfast(Cs);
                    }
                    *(float2*)(out + (size_t)row * 128 + ch) = make_float2(h2[0], h2[1]);
                }
            } else {
                float dg = rsqrtf(1.0f + (float)g_indeg[row]);
#pragma unroll
                for (int na = 0; na < 4; na++) {
                    int ch = wn * 32 + na * 8 + 2 * r;
                    *(float2*)(out + (size_t)row * 128 + ch) =
                        make_float2(C[0][ma][na][half * 2] * dg, C[0][ma][na][half * 2 + 1] * dg);
                }
            }
        }
    }
}

// ============================================================================
// gather + finalize: warp per node
// g = relu(dg*(self + sum_nbr hh[src]) + gcn_b); out = sum g*fa + fc
// ============================================================================
__global__ void gather_finalize(const float* __restrict__ gcn_b, float* __restrict__ out)
{
    int node = (blockIdx.x * blockDim.x + threadIdx.x) >> 5;
    int lane = threadIdx.x & 31;
    if (node >= N_NODES) return;
    int cnt = g_indeg[node];
    int base = g_off[node];
    float dg = rsqrtf(1.0f + (float)cnt);

    const float4* hh4 = (const float4*)g_hh;
    float4 acc = hh4[(size_t)node * 32 + lane];  // self term
    for (int e0 = 0; e0 < cnt; e0 += 32) {
        int myidx = (e0 + lane < cnt) ? g_csr[base + e0 + lane] : 0;
        int lim = min(32, cnt - e0);
        for (int t = 0; t < lim; t++) {
            int s = __shfl_sync(0xffffffffu, myidx, t);
            float4 v = __ldg(hh4 + (size_t)s * 32 + lane);
            acc.x += v.x; acc.y += v.y; acc.z += v.z; acc.w += v.w;
        }
    }

    float4 gb = ((const float4*)gcn_b)[lane];
    float4 fa = ((const float4*)g_fa)[lane];
    float sum = fmaxf(dg * acc.x + gb.x, 0.0f) * fa.x
              + fmaxf(dg * acc.y + gb.y, 0.0f) * fa.y
              + fmaxf(dg * acc.z + gb.z, 0.0f) * fa.z
              + fmaxf(dg * acc.w + gb.w, 0.0f) * fa.w;
#pragma unroll
    for (int o = 16; o > 0; o >>= 1) sum += __shfl_down_sync(0xffffffffu, sum, o);
    if (lane == 0) out[node] = sum + g_fc;
}

// ============================================================================
// launch
// ============================================================================
extern "C" void kernel_launch(void* const* d_in, const int* in_sizes, int n_in,
                              void* d_out, int out_size)
{
    const float* x        = (const float*)d_in[0];
    const int*   ei       = (const int*)  d_in[1];
    const float* W_x      = (const float*)d_in[3];
    const float* w_c      = (const float*)d_in[4];
    const float* b        = (const float*)d_in[5];
    const float* theta_b  = (const float*)d_in[7];
    const float* gcn_w    = (const float*)d_in[8];
    const float* gcn_b    = (const float*)d_in[9];
    const float* bn_gamma = (const float*)d_in[10];
    const float* bn_beta  = (const float*)d_in[11];
    const float* bn_mean  = (const float*)d_in[12];
    const float* bn_var   = (const float*)d_in[13];
    const float* lin_w    = (const float*)d_in[14];
    const float* lin_b    = (const float*)d_in[15];
    float* out = (float*)d_out;

    const int* src = ei;
    const int* dst = ei + N_EDGES;

    const int SM3 = 8704 * 4 * 4;  // 139264 B
    const int SM1 = 8704 * 2 * 4;  //  69632 B
    cudaFuncSetAttribute(gemm_tc<3>, cudaFuncAttributeMaxDynamicSharedMemorySize, SM3);
    cudaFuncSetAttribute(gemm_tc<1>, cudaFuncAttributeMaxDynamicSharedMemorySize, SM1);

    float *hsp, *hhp;
    cudaGetSymbolAddress((void**)&hsp, g_Hs);
    cudaGetSymbolAddress((void**)&hhp, g_hh);

    prep_kernel<<<1, 128>>>(theta_b, b, w_c, bn_gamma, bn_beta, bn_mean, bn_var, lin_w, lin_b);
    init_kernel<<<(N_NODES + 255) / 256, 256>>>();
    count_kernel<<<(N_EDGES + 255) / 256, 256>>>(dst);
    prefix_kernel<<<1, 1024>>>();
    fill_kernel<<<(N_EDGES + 255) / 256, 256>>>(src, dst);

    int mb = (N_NODES + 127) / 128;  // 391
    // fused 3-gate GEMM (i -> W_x[0], c -> W_x[2], o -> W_x[3]) + LSTM -> Hs
    gemm_tc<3><<<mb, 256, SM3>>>(x, W_x, W_x + 2 * 16384, W_x + 3 * 16384, hsp, N_NODES);
    // hh = rsqrt(1+indeg) * (Hs @ gcn_w)
    gemm_tc<1><<<mb, 256, SM1>>>(hsp, gcn_w, nullptr, nullptr, hhp, N_NODES);
    gather_finalize<<<(N_NODES * 32 + 255) / 256, 256>>>(gcn_b, out);
}

// round 4
// speedup vs baseline: 2.4697x; 1.2914x over previous
#include <cuda_runtime.h>
#include <cstdint>
#include <math.h>

#define N_NODES 50000
#define N_EDGES 640000
#define NH (N_NODES * 128)
#define NB 196  // ceil(N_NODES / 256)

// ---------------- scratch (static device globals) ---------------------------
__device__ float g_Hs[NH];            // LSTM hidden state
__device__ float g_hh[NH];            // dg[n] * (Hs @ gcn_w)[n]
__device__ int   g_indeg[N_NODES];
__device__ int   g_off[N_NODES + 1];
__device__ int   g_cursor[N_NODES];
__device__ int   g_csr[N_EDGES];
__device__ int   g_part[256];         // per-block partial sums (NB <= 256)
__device__ int   g_boff[256];         // exclusive block offsets
// fused per-channel constants
__device__ float g_cb0[128], g_cb1[128], g_cb2[128], g_wc2[128];
__device__ float g_fa[128];
__device__ float g_fc;

// ---------------- helpers ----------------------------------------------------
__device__ __forceinline__ float tanhfast(float x) {
    float r; asm("tanh.approx.f32 %0, %1;" : "=f"(r) : "f"(x)); return r;
}
__device__ __forceinline__ float sigfast(float x) {
    return 0.5f * tanhfast(0.5f * x) + 0.5f;
}
__device__ __forceinline__ uint32_t to_tf32(float x) {
    uint32_t u; asm("cvt.rna.tf32.f32 %0, %1;" : "=r"(u) : "f"(x)); return u;
}
__device__ __forceinline__ void mma_tf32(float* d, const uint32_t* a, uint32_t b0, uint32_t b1) {
    asm volatile(
        "mma.sync.aligned.m16n8k8.row.col.f32.tf32.tf32.f32 "
        "{%0,%1,%2,%3}, {%4,%5,%6,%7}, {%8,%9}, {%0,%1,%2,%3};"
        : "+f"(d[0]), "+f"(d[1]), "+f"(d[2]), "+f"(d[3])
        : "r"(a[0]), "r"(a[1]), "r"(a[2]), "r"(a[3]), "r"(b0), "r"(b1));
}

// ---------------- small kernels ----------------------------------------------
__global__ void prep_kernel(const float* __restrict__ theta_b, const float* __restrict__ b,
                            const float* __restrict__ w_c,
                            const float* __restrict__ gamma, const float* __restrict__ beta,
                            const float* __restrict__ mean, const float* __restrict__ var,
                            const float* __restrict__ lin_w, const float* __restrict__ lin_b) {
    int ch = threadIdx.x;  // 128
    g_cb0[ch] = theta_b[ch] + b[ch];                 // gate i
    g_cb1[ch] = theta_b[256 + ch] + b[256 + ch];     // gate c
    g_cb2[ch] = theta_b[384 + ch] + b[384 + ch];     // gate o
    g_wc2[ch] = w_c[256 + ch];
    float sc = gamma[ch] * rsqrtf(var[ch] + 1e-5f);
    g_fa[ch] = sc * lin_w[ch];
    __shared__ float red[128];
    red[ch] = (beta[ch] - mean[ch] * sc) * lin_w[ch];
    __syncthreads();
    for (int o = 64; o > 0; o >>= 1) { if (ch < o) red[ch] += red[ch + o]; __syncthreads(); }
    if (ch == 0) g_fc = red[0] + lin_b[0];
}

__global__ void init_kernel() {
    int i = blockIdx.x * blockDim.x + threadIdx.x;
    if (i < N_NODES) { g_indeg[i] = 0; g_cursor[i] = 0; }
}
__global__ void count_kernel(const int* __restrict__ dst) {
    int e = blockIdx.x * blockDim.x + threadIdx.x;
    if (e < N_EDGES) atomicAdd(&g_indeg[dst[e]], 1);
}

// ---- two-level scan: a) block partial sums, b) scan partials, c) local scan +
__global__ __launch_bounds__(256) void scan_a() {
    int i = blockIdx.x * 256 + threadIdx.x;
    int v = (i < N_NODES) ? g_indeg[i] : 0;
    int lane = threadIdx.x & 31, warp = threadIdx.x >> 5;
#pragma unroll
    for (int o = 16; o > 0; o >>= 1) v += __shfl_down_sync(0xffffffffu, v, o);
    __shared__ int ws[8];
    if (lane == 0) ws[warp] = v;
    __syncthreads();
    if (threadIdx.x == 0) {
        int s = 0;
#pragma unroll
        for (int w = 0; w < 8; w++) s += ws[w];
        g_part[blockIdx.x] = s;
    }
}
__global__ __launch_bounds__(256) void scan_b() {
    int t = threadIdx.x, lane = t & 31, warp = t >> 5;
    int v = (t < NB) ? g_part[t] : 0;
    int x = v;
#pragma unroll
    for (int o = 1; o < 32; o <<= 1) {
        int y = __shfl_up_sync(0xffffffffu, x, o);
        if (lane >= o) x += y;
    }
    __shared__ int ws[8];
    if (lane == 31) ws[warp] = x;
    __syncthreads();
    if (warp == 0 && lane < 8) {
        int w = ws[lane];
#pragma unroll
        for (int o = 1; o < 8; o <<= 1) {
            int y = __shfl_up_sync(0xffu, w, o);
            if (lane >= o) w += y;
        }
        ws[lane] = w;
    }
    __syncthreads();
    int incl = x + (warp > 0 ? ws[warp - 1] : 0);
    if (t < NB) g_boff[t] = incl - v;   // exclusive
}
__global__ __launch_bounds__(256) void scan_c() {
    int i = blockIdx.x * 256 + threadIdx.x;
    int t = threadIdx.x, lane = t & 31, warp = t >> 5;
    int v = (i < N_NODES) ? g_indeg[i] : 0;
    int x = v;
#pragma unroll
    for (int o = 1; o < 32; o <<= 1) {
        int y = __shfl_up_sync(0xffffffffu, x, o);
        if (lane >= o) x += y;
    }
    __shared__ int ws[8];
    if (lane == 31) ws[warp] = x;
    __syncthreads();
    if (warp == 0 && lane < 8) {
        int w = ws[lane];
#pragma unroll
        for (int o = 1; o < 8; o <<= 1) {
            int y = __shfl_up_sync(0xffu, w, o);
            if (lane >= o) w += y;
        }
        ws[lane] = w;
    }
    __syncthreads();
    int excl = x - v + (warp > 0 ? ws[warp - 1] : 0) + g_boff[blockIdx.x];
    if (i < N_NODES) g_off[i] = excl;
}

__global__ void fill_kernel(const int* __restrict__ src, const int* __restrict__ dst) {
    int e = blockIdx.x * blockDim.x + threadIdx.x;
    if (e >= N_EDGES) return;
    int d = dst[e];
    g_csr[g_off[d] + atomicAdd(&g_cursor[d], 1)] = src[e];
}

// ============================================================================
// tf32 mma.sync GEMM: out[128-tile,128] = A @ B  (B is [K=128][N=128] row-major)
// NG=3: gates i,c,o + fused LSTM -> Hs.   NG=1: fused rsqrt(1+indeg) scale -> hh.
// ============================================================================
template <int NG>
__global__ __launch_bounds__(256, 1) void gemm_tc(
    const float* __restrict__ A,
    const float* __restrict__ B0, const float* __restrict__ B1, const float* __restrict__ B2,
    float* __restrict__ out, int M)
{
    extern __shared__ uint32_t sm[];  // [0,8704): A ; [8704*(1+g), +8704): B_g
    const int tid = threadIdx.x, lane = tid & 31;
    const int wid = tid >> 5, wm = wid >> 2, wn = wid & 3;
    const int q = lane >> 2, r = lane & 3;
    const int rowblk = blockIdx.x * 128;
    const float* Bp[3] = { B0, B1, B2 };

    float C[NG][4][4][4];
#pragma unroll
    for (int g = 0; g < NG; g++)
#pragma unroll
        for (int i = 0; i < 4; i++)
#pragma unroll
            for (int j = 0; j < 4; j++)
#pragma unroll
                for (int k = 0; k < 4; k++) C[g][i][j][k] = 0.0f;

#pragma unroll
    for (int chunk = 0; chunk < 2; chunk++) {
        const int k0 = chunk * 64;
        if (chunk) __syncthreads();
        // ---- load A chunk: 128 rows x 64 k, pitch 68 ----
#pragma unroll
        for (int t = 0; t < 8; t++) {
            int i = tid + t * 256;            // 0..2047
            int row = i >> 4, j = i & 15;
            int gr = rowblk + row;
            float4 v = make_float4(0.f, 0.f, 0.f, 0.f);
            if (gr < M) v = *(const float4*)(A + (size_t)gr * 128 + k0 + j * 4);
            uint32_t* p = &sm[row * 68 + j * 4];
            p[0] = to_tf32(v.x); p[1] = to_tf32(v.y); p[2] = to_tf32(v.z); p[3] = to_tf32(v.w);
        }
        // ---- load B chunk(s): 64 k x 128 n, pitch 136 ----
#pragma unroll
        for (int g = 0; g < NG; g++) {
            const float* Bg = Bp[g];
            uint32_t* bs = sm + 8704 * (1 + g);
#pragma unroll
            for (int t = 0; t < 8; t++) {
                int i = tid + t * 256;
                int row = i >> 5, j = i & 31;
                float4 v = *(const float4*)(Bg + (size_t)(k0 + row) * 128 + j * 4);
                uint32_t* p = &bs[row * 136 + j * 4];
                p[0] = to_tf32(v.x); p[1] = to_tf32(v.y); p[2] = to_tf32(v.z); p[3] = to_tf32(v.w);
            }
        }
        __syncthreads();

        // ---- compute ----
#pragma unroll
        for (int ks = 0; ks < 8; ks++) {
            const int kb = ks * 8;
            uint32_t a[4][4];
#pragma unroll
            for (int ma = 0; ma < 4; ma++) {
                int m = wm * 64 + ma * 16 + q;
                const uint32_t* ap = &sm[m * 68 + kb + r];
                a[ma][0] = ap[0];
                a[ma][2] = ap[4];
                a[ma][1] = ap[8 * 68];
                a[ma][3] = ap[8 * 68 + 4];
            }
#pragma unroll
            for (int g = 0; g < NG; g++) {
                const uint32_t* bs = sm + 8704 * (1 + g);
#pragma unroll
                for (int na = 0; na < 4; na++) {
                    int n = wn * 32 + na * 8 + q;
                    const uint32_t* bp = &bs[(kb + r) * 136 + n];
                    uint32_t b0 = bp[0], b1 = bp[4 * 136];
#pragma unroll
                    for (int ma = 0; ma < 4; ma++) mma_tf32(C[g][ma][na], a[ma], b0, b1);
                }
            }
        }
    }

    // ---- epilogue ----
#pragma unroll
    for (int ma = 0; ma < 4; ma++) {
#pragma unroll
        for (int half = 0; half < 2; half++) {
            int row = rowblk + wm * 64 + ma * 16 + q + half * 8;
            if (row >= M) continue;
            if (NG == 3) {
#pragma unroll
                for (int na = 0; na < 4; na++) {
                    int ch = wn * 32 + na * 8 + 2 * r;
                    float h2[2];
#pragma unroll
                    for (int e = 0; e < 2; e++) {
                        int c = ch + e;
                        float zi = C[0][ma][na][half * 2 + e] + g_cb0[c];
                        float zc = C[NG > 1 ? 1 : 0][ma][na][half * 2 + e] + g_cb1[c];
                        float zo = C[NG > 1 ? 2 : 0][ma][na][half * 2 + e] + g_cb2[c];
                        float I = sigfast(zi);
                        float T = tanhfast(zc);
                        float Cs = I * T;
                        float O = sigfast(zo + g_wc2[c] * Cs);
                        h2[e] = O * tanhfast(Cs);
                    }
                    *(float2*)(out + (size_t)row * 128 + ch) = make_float2(h2[0], h2[1]);
                }
            } else {
                float dg = rsqrtf(1.0f + (float)g_indeg[row]);
#pragma unroll
                for (int na = 0; na < 4; na++) {
                    int ch = wn * 32 + na * 8 + 2 * r;
                    *(float2*)(out + (size_t)row * 128 + ch) =
                        make_float2(C[0][ma][na][half * 2] * dg, C[0][ma][na][half * 2 + 1] * dg);
                }
            }
        }
    }
}

// ============================================================================
// gather + finalize: warp per node
// ============================================================================
__global__ void gather_finalize(const float* __restrict__ gcn_b, float* __restrict__ out)
{
    int node = (blockIdx.x * blockDim.x + threadIdx.x) >> 5;
    int lane = threadIdx.x & 31;
    if (node >= N_NODES) return;
    int cnt = g_indeg[node];
    int base = g_off[node];
    float dg = rsqrtf(1.0f + (float)cnt);

    const float4* hh4 = (const float4*)g_hh;
    float4 acc = hh4[(size_t)node * 32 + lane];  // self term
    for (int e0 = 0; e0 < cnt; e0 += 32) {
        int myidx = (e0 + lane < cnt) ? g_csr[base + e0 + lane] : 0;
        int lim = min(32, cnt - e0);
        for (int t = 0; t < lim; t++) {
            int s = __shfl_sync(0xffffffffu, myidx, t);
            float4 v = __ldg(hh4 + (size_t)s * 32 + lane);
            acc.x += v.x; acc.y += v.y; acc.z += v.z; acc.w += v.w;
        }
    }

    float4 gb = ((const float4*)gcn_b)[lane];
    float4 fa = ((const float4*)g_fa)[lane];
    float sum = fmaxf(dg * acc.x + gb.x, 0.0f) * fa.x
              + fmaxf(dg * acc.y + gb.y, 0.0f) * fa.y
              + fmaxf(dg * acc.z + gb.z, 0.0f) * fa.z
              + fmaxf(dg * acc.w + gb.w, 0.0f) * fa.w;
#pragma unroll
    for (int o = 16; o > 0; o >>= 1) sum += __shfl_down_sync(0xffffffffu, sum, o);
    if (lane == 0) out[node] = sum + g_fc;
}

// ============================================================================
// launch
// ============================================================================
extern "C" void kernel_launch(void* const* d_in, const int* in_sizes, int n_in,
                              void* d_out, int out_size)
{
    const float* x        = (const float*)d_in[0];
    const int*   ei       = (const int*)  d_in[1];
    const float* W_x      = (const float*)d_in[3];
    const float* w_c      = (const float*)d_in[4];
    const float* b        = (const float*)d_in[5];
    const float* theta_b  = (const float*)d_in[7];
    const float* gcn_w    = (const float*)d_in[8];
    const float* gcn_b    = (const float*)d_in[9];
    const float* bn_gamma = (const float*)d_in[10];
    const float* bn_beta  = (const float*)d_in[11];
    const float* bn_mean  = (const float*)d_in[12];
    const float* bn_var   = (const float*)d_in[13];
    const float* lin_w    = (const float*)d_in[14];
    const float* lin_b    = (const float*)d_in[15];
    float* out = (float*)d_out;

    const int* src = ei;
    const int* dst = ei + N_EDGES;

    const int SM3 = 8704 * 4 * 4;  // 139264 B
    const int SM1 = 8704 * 2 * 4;  //  69632 B
    cudaFuncSetAttribute(gemm_tc<3>, cudaFuncAttributeMaxDynamicSharedMemorySize, SM3);
    cudaFuncSetAttribute(gemm_tc<1>, cudaFuncAttributeMaxDynamicSharedMemorySize, SM1);

    float *hsp, *hhp;
    cudaGetSymbolAddress((void**)&hsp, g_Hs);
    cudaGetSymbolAddress((void**)&hhp, g_hh);

    prep_kernel<<<1, 128>>>(theta_b, b, w_c, bn_gamma, bn_beta, bn_mean, bn_var, lin_w, lin_b);
    init_kernel<<<(N_NODES + 255) / 256, 256>>>();
    count_kernel<<<(N_EDGES + 255) / 256, 256>>>(dst);
    scan_a<<<NB, 256>>>();
    scan_b<<<1, 256>>>();
    scan_c<<<NB, 256>>>();
    fill_kernel<<<(N_EDGES + 255) / 256, 256>>>(src, dst);

    int mb = (N_NODES + 127) / 128;  // 391
    // fused 3-gate GEMM (i -> W_x[0], c -> W_x[2], o -> W_x[3]) + LSTM -> Hs
    gemm_tc<3><<<mb, 256, SM3>>>(x, W_x, W_x + 2 * 16384, W_x + 3 * 16384, hsp, N_NODES);
    // hh = rsqrt(1+indeg) * (Hs @ gcn_w)
    gemm_tc<1><<<mb, 256, SM1>>>(hsp, gcn_w, nullptr, nullptr, hhp, N_NODES);
    gather_finalize<<<(N_NODES * 32 + 255) / 256, 256>>>(gcn_b, out);
}

// round 5
// speedup vs baseline: 2.8527x; 1.1551x over previous
#include <cuda_runtime.h>
#include <cstdint>
#include <math.h>

#define N_NODES 50000
#define N_EDGES 640000
#define NH (N_NODES * 128)
#define NB 196  // ceil(N_NODES / 256)

// ---------------- scratch (static device globals) ---------------------------
__device__ float g_Hs[NH];            // LSTM hidden (stored tf32-rounded)
__device__ float g_hh[NH];            // dg[n] * (Hs @ gcn_w)[n]
__device__ uint32_t g_Wc[4 * 16384];  // tf32-converted weights: i, c, o, gcn_w
__device__ int   g_indeg[N_NODES];
__device__ int   g_off[N_NODES + 1];
__device__ int   g_cursor[N_NODES];
__device__ int   g_csr[N_EDGES];
__device__ int   g_part[256];
__device__ int   g_boff[256];
// fused per-channel constants
__device__ float g_cb0[128], g_cb1[128], g_cb2[128], g_wc2[128];
__device__ float g_fa[128];
__device__ float g_fc;

// ---------------- helpers ----------------------------------------------------
__device__ __forceinline__ float tanhfast(float x) {
    float r; asm("tanh.approx.f32 %0, %1;" : "=f"(r) : "f"(x)); return r;
}
__device__ __forceinline__ float sigfast(float x) {
    return 0.5f * tanhfast(0.5f * x) + 0.5f;
}
__device__ __forceinline__ uint32_t to_tf32(float x) {
    uint32_t u; asm("cvt.rna.tf32.f32 %0, %1;" : "=r"(u) : "f"(x)); return u;
}
__device__ __forceinline__ void mma_tf32(float* d, const uint32_t* a, uint32_t b0, uint32_t b1) {
    asm volatile(
        "mma.sync.aligned.m16n8k8.row.col.f32.tf32.tf32.f32 "
        "{%0,%1,%2,%3}, {%4,%5,%6,%7}, {%8,%9}, {%0,%1,%2,%3};"
        : "+f"(d[0]), "+f"(d[1]), "+f"(d[2]), "+f"(d[3])
        : "r"(a[0]), "r"(a[1]), "r"(a[2]), "r"(a[3]), "r"(b0), "r"(b1));
}
__device__ __forceinline__ uint32_t smem_u32(const void* p) {
    uint32_t a;
    asm("{ .reg .u64 t; cvta.to.shared.u64 t, %1; cvt.u32.u64 %0, t; }" : "=r"(a) : "l"(p));
    return a;
}
__device__ __forceinline__ void cp_async16(uint32_t daddr, const void* saddr, int srcsz) {
    asm volatile("cp.async.cg.shared.global [%0], [%1], 16, %2;"
                 :: "r"(daddr), "l"(saddr), "r"(srcsz) : "memory");
}
__device__ __forceinline__ void cp_commit_wait() {
    asm volatile("cp.async.commit_group;" ::: "memory");
    asm volatile("cp.async.wait_group 0;" ::: "memory");
}

// ---------------- small kernels ----------------------------------------------
__global__ void prep_kernel(const float* __restrict__ theta_b, const float* __restrict__ b,
                            const float* __restrict__ w_c,
                            const float* __restrict__ gamma, const float* __restrict__ beta,
                            const float* __restrict__ mean, const float* __restrict__ var,
                            const float* __restrict__ lin_w, const float* __restrict__ lin_b) {
    int ch = threadIdx.x;  // 128
    g_cb0[ch] = theta_b[ch] + b[ch];                 // gate i
    g_cb1[ch] = theta_b[256 + ch] + b[256 + ch];     // gate c
    g_cb2[ch] = theta_b[384 + ch] + b[384 + ch];     // gate o
    g_wc2[ch] = w_c[256 + ch];
    float sc = gamma[ch] * rsqrtf(var[ch] + 1e-5f);
    g_fa[ch] = sc * lin_w[ch];
    __shared__ float red[128];
    red[ch] = (beta[ch] - mean[ch] * sc) * lin_w[ch];
    __syncthreads();
    for (int o = 64; o > 0; o >>= 1) { if (ch < o) red[ch] += red[ch + o]; __syncthreads(); }
    if (ch == 0) g_fc = red[0] + lin_b[0];
}

// convert weights to tf32 once: matrices {W_x[0], W_x[2], W_x[3], gcn_w}
__global__ void prep_w(const float* __restrict__ Wx, const float* __restrict__ gcn) {
    int i = blockIdx.x * 256 + threadIdx.x;   // 0..65535
    int m = i >> 14, r = i & 16383;
    const float* S = (m == 0) ? Wx
                   : (m == 1) ? Wx + 2 * 16384
                   : (m == 2) ? Wx + 3 * 16384 : gcn;
    g_Wc[i] = to_tf32(S[r]);
}

__global__ void init_kernel() {
    int i = blockIdx.x * blockDim.x + threadIdx.x;
    if (i < N_NODES) { g_indeg[i] = 0; g_cursor[i] = 0; }
}
__global__ void count_kernel(const int* __restrict__ dst) {
    int e = blockIdx.x * blockDim.x + threadIdx.x;
    if (e < N_EDGES) atomicAdd(&g_indeg[dst[e]], 1);
}

// ---- two-level scan ----
__global__ __launch_bounds__(256) void scan_a() {
    int i = blockIdx.x * 256 + threadIdx.x;
    int v = (i < N_NODES) ? g_indeg[i] : 0;
    int lane = threadIdx.x & 31, warp = threadIdx.x >> 5;
#pragma unroll
    for (int o = 16; o > 0; o >>= 1) v += __shfl_down_sync(0xffffffffu, v, o);
    __shared__ int ws[8];
    if (lane == 0) ws[warp] = v;
    __syncthreads();
    if (threadIdx.x == 0) {
        int s = 0;
#pragma unroll
        for (int w = 0; w < 8; w++) s += ws[w];
        g_part[blockIdx.x] = s;
    }
}
__global__ __launch_bounds__(256) void scan_b() {
    int t = threadIdx.x, lane = t & 31, warp = t >> 5;
    int v = (t < NB) ? g_part[t] : 0;
    int x = v;
#pragma unroll
    for (int o = 1; o < 32; o <<= 1) {
        int y = __shfl_up_sync(0xffffffffu, x, o);
        if (lane >= o) x += y;
    }
    __shared__ int ws[8];
    if (lane == 31) ws[warp] = x;
    __syncthreads();
    if (warp == 0 && lane < 8) {
        int w = ws[lane];
#pragma unroll
        for (int o = 1; o < 8; o <<= 1) {
            int y = __shfl_up_sync(0xffu, w, o);
            if (lane >= o) w += y;
        }
        ws[lane] = w;
    }
    __syncthreads();
    int incl = x + (warp > 0 ? ws[warp - 1] : 0);
    if (t < NB) g_boff[t] = incl - v;
}
__global__ __launch_bounds__(256) void scan_c() {
    int i = blockIdx.x * 256 + threadIdx.x;
    int t = threadIdx.x, lane = t & 31, warp = t >> 5;
    int v = (i < N_NODES) ? g_indeg[i] : 0;
    int x = v;
#pragma unroll
    for (int o = 1; o < 32; o <<= 1) {
        int y = __shfl_up_sync(0xffffffffu, x, o);
        if (lane >= o) x += y;
    }
    __shared__ int ws[8];
    if (lane == 31) ws[warp] = x;
    __syncthreads();
    if (warp == 0 && lane < 8) {
        int w = ws[lane];
#pragma unroll
        for (int o = 1; o < 8; o <<= 1) {
            int y = __shfl_up_sync(0xffu, w, o);
            if (lane >= o) w += y;
        }
        ws[lane] = w;
    }
    __syncthreads();
    int excl = x - v + (warp > 0 ? ws[warp - 1] : 0) + g_boff[blockIdx.x];
    if (i < N_NODES) g_off[i] = excl;
}

__global__ void fill_kernel(const int* __restrict__ src, const int* __restrict__ dst) {
    int e = blockIdx.x * blockDim.x + threadIdx.x;
    if (e >= N_EDGES) return;
    int d = dst[e];
    g_csr[g_off[d] + atomicAdd(&g_cursor[d], 1)] = src[e];
}

// ============================================================================
// tf32 mma.sync GEMM. B operands are pre-converted tf32 bits in g_Wc.
// NG=3 + ACP=0: gates + fused LSTM -> Hs (tf32-rounded); A via register+cvt.
// NG=1 + ACP=1: A (=Hs, already tf32 bits) via cp.async; fused dg scale -> hh.
// ============================================================================
template <int NG, int ACP>
__global__ __launch_bounds__(256, 1) void gemm_tc(
    const float* __restrict__ A,
    const uint32_t* __restrict__ B0, const uint32_t* __restrict__ B1,
    const uint32_t* __restrict__ B2,
    float* __restrict__ out, int M)
{
    extern __shared__ uint32_t sm[];  // [0,8704): A ; [8704*(1+g), +8704): B_g
    const int tid = threadIdx.x, lane = tid & 31;
    const int wid = tid >> 5, wm = wid >> 2, wn = wid & 3;
    const int q = lane >> 2, r = lane & 3;
    const int rowblk = blockIdx.x * 128;
    const uint32_t* Bp[3] = { B0, B1, B2 };
    const uint32_t sbase = smem_u32(sm);

    float C[NG][4][4][4];
#pragma unroll
    for (int g = 0; g < NG; g++)
#pragma unroll
        for (int i = 0; i < 4; i++)
#pragma unroll
            for (int j = 0; j < 4; j++)
#pragma unroll
                for (int k = 0; k < 4; k++) C[g][i][j][k] = 0.0f;

#pragma unroll
    for (int chunk = 0; chunk < 2; chunk++) {
        const int k0 = chunk * 64;
        if (chunk) __syncthreads();

        // ---- B chunk(s) via cp.async: 64 k x 128 n, pitch 136 ----
#pragma unroll
        for (int g = 0; g < NG; g++) {
            const uint32_t* Bg = Bp[g];
#pragma unroll
            for (int t = 0; t < 8; t++) {
                int i = tid + t * 256;
                int row = i >> 5, j = i & 31;
                cp_async16(sbase + (8704 * (1 + g) + row * 136 + j * 4) * 4,
                           Bg + (size_t)(k0 + row) * 128 + j * 4, 16);
            }
        }
        // ---- A chunk: 128 rows x 64 k, pitch 68 ----
        if (ACP) {
#pragma unroll
            for (int t = 0; t < 8; t++) {
                int i = tid + t * 256;
                int row = i >> 4, j = i & 15;
                int gr = rowblk + row;
                cp_async16(sbase + (row * 68 + j * 4) * 4,
                           A + (size_t)gr * 128 + k0 + j * 4,
                           (gr < M) ? 16 : 0);
            }
            cp_commit_wait();
        } else {
            asm volatile("cp.async.commit_group;" ::: "memory");
#pragma unroll
            for (int t = 0; t < 8; t++) {
                int i = tid + t * 256;
                int row = i >> 4, j = i & 15;
                int gr = rowblk + row;
                float4 v = make_float4(0.f, 0.f, 0.f, 0.f);
                if (gr < M) v = *(const float4*)(A + (size_t)gr * 128 + k0 + j * 4);
                uint32_t* p = &sm[row * 68 + j * 4];
                p[0] = to_tf32(v.x); p[1] = to_tf32(v.y);
                p[2] = to_tf32(v.z); p[3] = to_tf32(v.w);
            }
            asm volatile("cp.async.wait_group 0;" ::: "memory");
        }
        __syncthreads();

        // ---- compute ----
#pragma unroll
        for (int ks = 0; ks < 8; ks++) {
            const int kb = ks * 8;
            uint32_t a[4][4];
#pragma unroll
            for (int ma = 0; ma < 4; ma++) {
                int m = wm * 64 + ma * 16 + q;
                const uint32_t* ap = &sm[m * 68 + kb + r];
                a[ma][0] = ap[0];
                a[ma][2] = ap[4];
                a[ma][1] = ap[8 * 68];
                a[ma][3] = ap[8 * 68 + 4];
            }
#pragma unroll
            for (int g = 0; g < NG; g++) {
                const uint32_t* bs = sm + 8704 * (1 + g);
#pragma unroll
                for (int na = 0; na < 4; na++) {
                    int n = wn * 32 + na * 8 + q;
                    const uint32_t* bp = &bs[(kb + r) * 136 + n];
                    uint32_t b0 = bp[0], b1 = bp[4 * 136];
#pragma unroll
                    for (int ma = 0; ma < 4; ma++) mma_tf32(C[g][ma][na], a[ma], b0, b1);
                }
            }
        }
    }

    // ---- epilogue ----
#pragma unroll
    for (int ma = 0; ma < 4; ma++) {
#pragma unroll
        for (int half = 0; half < 2; half++) {
            int row = rowblk + wm * 64 + ma * 16 + q + half * 8;
            if (row >= M) continue;
            if (NG == 3) {
#pragma unroll
                for (int na = 0; na < 4; na++) {
                    int ch = wn * 32 + na * 8 + 2 * r;
                    float h2[2];
#pragma unroll
                    for (int e = 0; e < 2; e++) {
                        int c = ch + e;
                        float zi = C[0][ma][na][half * 2 + e] + g_cb0[c];
                        float zc = C[NG > 1 ? 1 : 0][ma][na][half * 2 + e] + g_cb1[c];
                        float zo = C[NG > 1 ? 2 : 0][ma][na][half * 2 + e] + g_cb2[c];
                        float I = sigfast(zi);
                        float T = tanhfast(zc);
                        float Cs = I * T;
                        float O = sigfast(zo + g_wc2[c] * Cs);
                        // store tf32-rounded so gemm1 can consume raw bits
                        h2[e] = __uint_as_float(to_tf32(O * tanhfast(Cs)));
                    }
                    *(float2*)(out + (size_t)row * 128 + ch) = make_float2(h2[0], h2[1]);
                }
            } else {
                float dg = rsqrtf(1.0f + (float)g_indeg[row]);
#pragma unroll
                for (int na = 0; na < 4; na++) {
                    int ch = wn * 32 + na * 8 + 2 * r;
                    *(float2*)(out + (size_t)row * 128 + ch) =
                        make_float2(C[0][ma][na][half * 2] * dg, C[0][ma][na][half * 2 + 1] * dg);
                }
            }
        }
    }
}

// ============================================================================
// gather + finalize: warp per node
// ============================================================================
__global__ __launch_bounds__(256) void gather_finalize(const float* __restrict__ gcn_b,
                                                       float* __restrict__ out)
{
    int node = (blockIdx.x * blockDim.x + threadIdx.x) >> 5;
    int lane = threadIdx.x & 31;
    if (node >= N_NODES) return;
    int cnt = g_indeg[node];
    int base = g_off[node];
    float dg = rsqrtf(1.0f + (float)cnt);

    const float4* hh4 = (const float4*)g_hh;
    float4 acc = hh4[(size_t)node * 32 + lane];  // self term
    for (int e0 = 0; e0 < cnt; e0 += 32) {
        int myidx = (e0 + lane < cnt) ? g_csr[base + e0 + lane] : 0;
        int lim = min(32, cnt - e0);
        for (int t = 0; t < lim; t++) {
            int s = __shfl_sync(0xffffffffu, myidx, t);
            float4 v = __ldg(hh4 + (size_t)s * 32 + lane);
            acc.x += v.x; acc.y += v.y; acc.z += v.z; acc.w += v.w;
        }
    }

    float4 gb = ((const float4*)gcn_b)[lane];
    float4 fa = ((const float4*)g_fa)[lane];
    float sum = fmaxf(dg * acc.x + gb.x, 0.0f) * fa.x
              + fmaxf(dg * acc.y + gb.y, 0.0f) * fa.y
              + fmaxf(dg * acc.z + gb.z, 0.0f) * fa.z
              + fmaxf(dg * acc.w + gb.w, 0.0f) * fa.w;
#pragma unroll
    for (int o = 16; o > 0; o >>= 1) sum += __shfl_down_sync(0xffffffffu, sum, o);
    if (lane == 0) out[node] = sum + g_fc;
}

// ============================================================================
// launch: fork CSR build onto a side stream; join via events.
// ============================================================================
extern "C" void kernel_launch(void* const* d_in, const int* in_sizes, int n_in,
                              void* d_out, int out_size)
{
    const float* x        = (const float*)d_in[0];
    const int*   ei       = (const int*)  d_in[1];
    const float* W_x      = (const float*)d_in[3];
    const float* w_c      = (const float*)d_in[4];
    const float* b        = (const float*)d_in[5];
    const float* theta_b  = (const float*)d_in[7];
    const float* gcn_w    = (const float*)d_in[8];
    const float* gcn_b    = (const float*)d_in[9];
    const float* bn_gamma = (const float*)d_in[10];
    const float* bn_beta  = (const float*)d_in[11];
    const float* bn_mean  = (const float*)d_in[12];
    const float* bn_var   = (const float*)d_in[13];
    const float* lin_w    = (const float*)d_in[14];
    const float* lin_b    = (const float*)d_in[15];
    float* out = (float*)d_out;

    const int* src = ei;
    const int* dst = ei + N_EDGES;

    const int SM3 = 8704 * 4 * 4;  // 139264 B
    const int SM1 = 8704 * 2 * 4;  //  69632 B

    static cudaStream_t s1 = nullptr;
    static cudaEvent_t evRoot, evCnt, evCsr;
    if (!s1) {
        cudaStreamCreateWithFlags(&s1, cudaStreamNonBlocking);
        cudaEventCreateWithFlags(&evRoot, cudaEventDisableTiming);
        cudaEventCreateWithFlags(&evCnt,  cudaEventDisableTiming);
        cudaEventCreateWithFlags(&evCsr,  cudaEventDisableTiming);
        cudaFuncSetAttribute((const void*)gemm_tc<3, 0>,
                             cudaFuncAttributeMaxDynamicSharedMemorySize, SM3);
        cudaFuncSetAttribute((const void*)gemm_tc<1, 1>,
                             cudaFuncAttributeMaxDynamicSharedMemorySize, SM1);
    }

    float *hsp, *hhp;
    uint32_t* wcp;
    cudaGetSymbolAddress((void**)&hsp, g_Hs);
    cudaGetSymbolAddress((void**)&hhp, g_hh);
    cudaGetSymbolAddress((void**)&wcp, g_Wc);

    // fork
    cudaEventRecord(evRoot, 0);
    cudaStreamWaitEvent(s1, evRoot, 0);

    // ---- branch B (s1): CSR build ----
    init_kernel<<<(N_NODES + 255) / 256, 256, 0, s1>>>();
    count_kernel<<<(N_EDGES + 255) / 256, 256, 0, s1>>>(dst);
    cudaEventRecord(evCnt, s1);
    scan_a<<<NB, 256, 0, s1>>>();
    scan_b<<<1, 256, 0, s1>>>();
    scan_c<<<NB, 256, 0, s1>>>();
    fill_kernel<<<(N_EDGES + 255) / 256, 256, 0, s1>>>(src, dst);
    cudaEventRecord(evCsr, s1);

    // ---- branch A (main): weights + gate GEMM ----
    prep_kernel<<<1, 128>>>(theta_b, b, w_c, bn_gamma, bn_beta, bn_mean, bn_var, lin_w, lin_b);
    prep_w<<<256, 256>>>(W_x, gcn_w);

    int mb = (N_NODES + 127) / 128;  // 391
    gemm_tc<3, 0><<<mb, 256, SM3>>>(x, wcp, wcp + 16384, wcp + 2 * 16384, hsp, N_NODES);

    cudaStreamWaitEvent(0, evCnt, 0);   // gemm1 needs indeg
    gemm_tc<1, 1><<<mb, 256, SM1>>>(hsp, wcp + 3 * 16384, nullptr, nullptr, hhp, N_NODES);

    cudaStreamWaitEvent(0, evCsr, 0);   // gather needs CSR
    gather_finalize<<<(N_NODES * 32 + 255) / 256, 256>>>(gcn_b, out);
}

// round 6
// speedup vs baseline: 2.9192x; 1.0233x over previous
#include <cuda_runtime.h>
#include <cstdint>
#include <math.h>

#define N_NODES 50000
#define N_EDGES 640000
#define NH (N_NODES * 128)
#define NB 196  // ceil(N_NODES / 256)

// ---------------- scratch (static device globals) ---------------------------
__device__ float g_Hs[NH];            // LSTM hidden (stored tf32-rounded)
__device__ float g_hh[NH];            // dg[n] * (Hs @ gcn_w)[n]
__device__ uint32_t g_Wc[4 * 16384];  // tf32-converted weights: i, c, o, gcn_w
__device__ int   g_indeg[N_NODES];
__device__ int   g_off[N_NODES + 1];
__device__ int   g_cursor[N_NODES];
__device__ int   g_csr[N_EDGES];
__device__ int   g_part[256];
__device__ int   g_boff[256];
// fused per-channel constants
__device__ float g_cb0[128], g_cb1[128], g_cb2[128], g_wc2[128];
__device__ float g_fa[128];
__device__ float g_fc;

// ---------------- helpers ----------------------------------------------------
__device__ __forceinline__ float tanhfast(float x) {
    float r; asm("tanh.approx.f32 %0, %1;" : "=f"(r) : "f"(x)); return r;
}
__device__ __forceinline__ float sigfast(float x) {
    return 0.5f * tanhfast(0.5f * x) + 0.5f;
}
__device__ __forceinline__ uint32_t to_tf32(float x) {
    uint32_t u; asm("cvt.rna.tf32.f32 %0, %1;" : "=r"(u) : "f"(x)); return u;
}
__device__ __forceinline__ void mma_tf32(float* d, const uint32_t* a, uint32_t b0, uint32_t b1) {
    asm volatile(
        "mma.sync.aligned.m16n8k8.row.col.f32.tf32.tf32.f32 "
        "{%0,%1,%2,%3}, {%4,%5,%6,%7}, {%8,%9}, {%0,%1,%2,%3};"
        : "+f"(d[0]), "+f"(d[1]), "+f"(d[2]), "+f"(d[3])
        : "r"(a[0]), "r"(a[1]), "r"(a[2]), "r"(a[3]), "r"(b0), "r"(b1));
}
__device__ __forceinline__ uint32_t smem_u32(const void* p) {
    uint32_t a;
    asm("{ .reg .u64 t; cvta.to.shared.u64 t, %1; cvt.u32.u64 %0, t; }" : "=r"(a) : "l"(p));
    return a;
}
__device__ __forceinline__ void cp_async16(uint32_t daddr, const void* saddr, int srcsz) {
    asm volatile("cp.async.cg.shared.global [%0], [%1], 16, %2;"
                 :: "r"(daddr), "l"(saddr), "r"(srcsz) : "memory");
}

// ---------------- fused prep: weights->tf32 + per-channel constants ----------
__global__ void prep_all(const float* __restrict__ Wx, const float* __restrict__ gcn,
                         const float* __restrict__ theta_b, const float* __restrict__ b,
                         const float* __restrict__ w_c,
                         const float* __restrict__ gamma, const float* __restrict__ beta,
                         const float* __restrict__ mean, const float* __restrict__ var,
                         const float* __restrict__ lin_w, const float* __restrict__ lin_b) {
    if (blockIdx.x < 256) {
        int i = blockIdx.x * 256 + threadIdx.x;   // 0..65535
        int m = i >> 14, r = i & 16383;
        const float* S = (m == 0) ? Wx
                       : (m == 1) ? Wx + 2 * 16384
                       : (m == 2) ? Wx + 3 * 16384 : gcn;
        g_Wc[i] = to_tf32(S[r]);
        return;
    }
    int ch = threadIdx.x;
    if (ch >= 128) return;
    g_cb0[ch] = theta_b[ch] + b[ch];
    g_cb1[ch] = theta_b[256 + ch] + b[256 + ch];
    g_cb2[ch] = theta_b[384 + ch] + b[384 + ch];
    g_wc2[ch] = w_c[256 + ch];
    float sc = gamma[ch] * rsqrtf(var[ch] + 1e-5f);
    g_fa[ch] = sc * lin_w[ch];
    __shared__ float red[128];
    red[ch] = (beta[ch] - mean[ch] * sc) * lin_w[ch];
    __syncthreads();
    for (int o = 64; o > 0; o >>= 1) { if (ch < o) red[ch] += red[ch + o]; __syncthreads(); }
    if (ch == 0) g_fc = red[0] + lin_b[0];
}

__global__ void init_kernel() {
    int i = blockIdx.x * blockDim.x + threadIdx.x;
    if (i < N_NODES) { g_indeg[i] = 0; g_cursor[i] = 0; }
}
__global__ void count_kernel(const int* __restrict__ dst) {
    int e = blockIdx.x * blockDim.x + threadIdx.x;
    if (e < N_EDGES) atomicAdd(&g_indeg[dst[e]], 1);
}

// ---- two-level scan ----
__global__ __launch_bounds__(256) void scan_a() {
    int i = blockIdx.x * 256 + threadIdx.x;
    int v = (i < N_NODES) ? g_indeg[i] : 0;
    int lane = threadIdx.x & 31, warp = threadIdx.x >> 5;
#pragma unroll
    for (int o = 16; o > 0; o >>= 1) v += __shfl_down_sync(0xffffffffu, v, o);
    __shared__ int ws[8];
    if (lane == 0) ws[warp] = v;
    __syncthreads();
    if (threadIdx.x == 0) {
        int s = 0;
#pragma unroll
        for (int w = 0; w < 8; w++) s += ws[w];
        g_part[blockIdx.x] = s;
    }
}
__global__ __launch_bounds__(256) void scan_b() {
    int t = threadIdx.x, lane = t & 31, warp = t >> 5;
    int v = (t < NB) ? g_part[t] : 0;
    int x = v;
#pragma unroll
    for (int o = 1; o < 32; o <<= 1) {
        int y = __shfl_up_sync(0xffffffffu, x, o);
        if (lane >= o) x += y;
    }
    __shared__ int ws[8];
    if (lane == 31) ws[warp] = x;
    __syncthreads();
    if (warp == 0 && lane < 8) {
        int w = ws[lane];
#pragma unroll
        for (int o = 1; o < 8; o <<= 1) {
            int y = __shfl_up_sync(0xffu, w, o);
            if (lane >= o) w += y;
        }
        ws[lane] = w;
    }
    __syncthreads();
    int incl = x + (warp > 0 ? ws[warp - 1] : 0);
    if (t < NB) g_boff[t] = incl - v;
}
__global__ __launch_bounds__(256) void scan_c() {
    int i = blockIdx.x * 256 + threadIdx.x;
    int t = threadIdx.x, lane = t & 31, warp = t >> 5;
    int v = (i < N_NODES) ? g_indeg[i] : 0;
    int x = v;
#pragma unroll
    for (int o = 1; o < 32; o <<= 1) {
        int y = __shfl_up_sync(0xffffffffu, x, o);
        if (lane >= o) x += y;
    }
    __shared__ int ws[8];
    if (lane == 31) ws[warp] = x;
    __syncthreads();
    if (warp == 0 && lane < 8) {
        int w = ws[lane];
#pragma unroll
        for (int o = 1; o < 8; o <<= 1) {
            int y = __shfl_up_sync(0xffu, w, o);
            if (lane >= o) w += y;
        }
        ws[lane] = w;
    }
    __syncthreads();
    int excl = x - v + (warp > 0 ? ws[warp - 1] : 0) + g_boff[blockIdx.x];
    if (i < N_NODES) g_off[i] = excl;
}

__global__ void fill_kernel(const int* __restrict__ src, const int* __restrict__ dst) {
    int e = blockIdx.x * blockDim.x + threadIdx.x;
    if (e >= N_EDGES) return;
    int d = dst[e];
    g_csr[g_off[d] + atomicAdd(&g_cursor[d], 1)] = src[e];
}

// ============================================================================
// tf32 mma.sync GEMM, 512 threads, 16 warps (4m x 4n), warp tile 32x32.
// B operands pre-converted tf32 bits. A/out/indeg pointers pre-offset per half.
// NG=3, ACP=0: gates + fused LSTM -> Hs (tf32-rounded).
// NG=1, ACP=1: A already tf32 bits, cp.async; fused rsqrt(1+indeg) scale -> hh.
// smem: A [128][68] ; B_g [64][136] at 8704*(1+g)
// ============================================================================
template <int NG, int ACP>
__global__ __launch_bounds__(512, 1) void gemm_tc(
    const float* __restrict__ A,
    const uint32_t* __restrict__ B0, const uint32_t* __restrict__ B1,
    const uint32_t* __restrict__ B2,
    float* __restrict__ out, int M, const int* __restrict__ indeg)
{
    extern __shared__ uint32_t sm[];
    const int tid = threadIdx.x, lane = tid & 31;
    const int wid = tid >> 5, wm = wid >> 2, wn = wid & 3;
    const int q = lane >> 2, r = lane & 3;
    const int rowblk = blockIdx.x * 128;
    const uint32_t* Bp[3] = { B0, B1, B2 };
    const uint32_t sbase = smem_u32(sm);

    float C[NG][2][4][4];
#pragma unroll
    for (int g = 0; g < NG; g++)
#pragma unroll
        for (int i = 0; i < 2; i++)
#pragma unroll
            for (int j = 0; j < 4; j++)
#pragma unroll
                for (int k = 0; k < 4; k++) C[g][i][j][k] = 0.0f;

#pragma unroll
    for (int chunk = 0; chunk < 2; chunk++) {
        const int k0 = chunk * 64;
        if (chunk) __syncthreads();

        // ---- B chunk(s) via cp.async: 64 k x 128 n, pitch 136 ----
#pragma unroll
        for (int g = 0; g < NG; g++) {
            const uint32_t* Bg = Bp[g];
#pragma unroll
            for (int t = 0; t < 4; t++) {
                int i = tid + t * 512;
                int row = i >> 5, j = i & 31;
                cp_async16(sbase + (8704 * (1 + g) + row * 136 + j * 4) * 4,
                           Bg + (size_t)(k0 + row) * 128 + j * 4, 16);
            }
        }
        // ---- A chunk: 128 rows x 64 k, pitch 68 ----
        if (ACP) {
#pragma unroll
            for (int t = 0; t < 4; t++) {
                int i = tid + t * 512;
                int row = i >> 4, j = i & 15;
                int gr = rowblk + row;
                cp_async16(sbase + (row * 68 + j * 4) * 4,
                           A + (size_t)gr * 128 + k0 + j * 4,
                           (gr < M) ? 16 : 0);
            }
            asm volatile("cp.async.commit_group;" ::: "memory");
            asm volatile("cp.async.wait_group 0;" ::: "memory");
        } else {
            asm volatile("cp.async.commit_group;" ::: "memory");
#pragma unroll
            for (int t = 0; t < 4; t++) {
                int i = tid + t * 512;
                int row = i >> 4, j = i & 15;
                int gr = rowblk + row;
                float4 v = make_float4(0.f, 0.f, 0.f, 0.f);
                if (gr < M) v = *(const float4*)(A + (size_t)gr * 128 + k0 + j * 4);
                uint32_t* p = &sm[row * 68 + j * 4];
                p[0] = to_tf32(v.x); p[1] = to_tf32(v.y);
                p[2] = to_tf32(v.z); p[3] = to_tf32(v.w);
            }
            asm volatile("cp.async.wait_group 0;" ::: "memory");
        }
        __syncthreads();

        // ---- compute ----
#pragma unroll
        for (int ks = 0; ks < 8; ks++) {
            const int kb = ks * 8;
            uint32_t a[2][4];
#pragma unroll
            for (int ma = 0; ma < 2; ma++) {
                int m = wm * 32 + ma * 16 + q;
                const uint32_t* ap = &sm[m * 68 + kb + r];
                a[ma][0] = ap[0];
                a[ma][2] = ap[4];
                a[ma][1] = ap[8 * 68];
                a[ma][3] = ap[8 * 68 + 4];
            }
#pragma unroll
            for (int g = 0; g < NG; g++) {
                const uint32_t* bs = sm + 8704 * (1 + g);
#pragma unroll
                for (int na = 0; na < 4; na++) {
                    int n = wn * 32 + na * 8 + q;
                    const uint32_t* bp = &bs[(kb + r) * 136 + n];
                    uint32_t b0 = bp[0], b1 = bp[4 * 136];
#pragma unroll
                    for (int ma = 0; ma < 2; ma++) mma_tf32(C[g][ma][na], a[ma], b0, b1);
                }
            }
        }
    }

    // ---- epilogue ----
#pragma unroll
    for (int ma = 0; ma < 2; ma++) {
#pragma unroll
        for (int half = 0; half < 2; half++) {
            int row = rowblk + wm * 32 + ma * 16 + q + half * 8;
            if (row >= M) continue;
            if (NG == 3) {
#pragma unroll
                for (int na = 0; na < 4; na++) {
                    int ch = wn * 32 + na * 8 + 2 * r;
                    float h2[2];
#pragma unroll
                    for (int e = 0; e < 2; e++) {
                        int c = ch + e;
                        float zi = C[0][ma][na][half * 2 + e] + g_cb0[c];
                        float zc = C[NG > 1 ? 1 : 0][ma][na][half * 2 + e] + g_cb1[c];
                        float zo = C[NG > 1 ? 2 : 0][ma][na][half * 2 + e] + g_cb2[c];
                        float I = sigfast(zi);
                        float T = tanhfast(zc);
                        float Cs = I * T;
                        float O = sigfast(zo + g_wc2[c] * Cs);
                        h2[e] = __uint_as_float(to_tf32(O * tanhfast(Cs)));
                    }
                    *(float2*)(out + (size_t)row * 128 + ch) = make_float2(h2[0], h2[1]);
                }
            } else {
                float dg = rsqrtf(1.0f + (float)indeg[row]);
#pragma unroll
                for (int na = 0; na < 4; na++) {
                    int ch = wn * 32 + na * 8 + 2 * r;
                    *(float2*)(out + (size_t)row * 128 + ch) =
                        make_float2(C[0][ma][na][half * 2] * dg, C[0][ma][na][half * 2 + 1] * dg);
                }
            }
        }
    }
}

// ============================================================================
// gather + finalize: warp per node
// ============================================================================
__global__ __launch_bounds__(256) void gather_finalize(const float* __restrict__ gcn_b,
                                                       float* __restrict__ out)
{
    int node = (blockIdx.x * blockDim.x + threadIdx.x) >> 5;
    int lane = threadIdx.x & 31;
    if (node >= N_NODES) return;
    int cnt = g_indeg[node];
    int base = g_off[node];
    float dg = rsqrtf(1.0f + (float)cnt);

    const float4* hh4 = (const float4*)g_hh;
    float4 acc = hh4[(size_t)node * 32 + lane];  // self term
    for (int e0 = 0; e0 < cnt; e0 += 32) {
        int myidx = (e0 + lane < cnt) ? g_csr[base + e0 + lane] : 0;
        int lim = min(32, cnt - e0);
        for (int t = 0; t < lim; t++) {
            int s = __shfl_sync(0xffffffffu, myidx, t);
            float4 v = __ldg(hh4 + (size_t)s * 32 + lane);
            acc.x += v.x; acc.y += v.y; acc.z += v.z; acc.w += v.w;
        }
    }

    float4 gb = ((const float4*)gcn_b)[lane];
    float4 fa = ((const float4*)g_fa)[lane];
    float sum = fmaxf(dg * acc.x + gb.x, 0.0f) * fa.x
              + fmaxf(dg * acc.y + gb.y, 0.0f) * fa.y
              + fmaxf(dg * acc.z + gb.z, 0.0f) * fa.z
              + fmaxf(dg * acc.w + gb.w, 0.0f) * fa.w;
#pragma unroll
    for (int o = 16; o > 0; o >>= 1) sum += __shfl_down_sync(0xffffffffu, sum, o);
    if (lane == 0) out[node] = sum + g_fc;
}

// ============================================================================
// launch: CSR on side stream; split-half GEMM pipeline across streams.
// ============================================================================
extern "C" void kernel_launch(void* const* d_in, const int* in_sizes, int n_in,
                              void* d_out, int out_size)
{
    const float* x        = (const float*)d_in[0];
    const int*   ei       = (const int*)  d_in[1];
    const float* W_x      = (const float*)d_in[3];
    const float* w_c      = (const float*)d_in[4];
    const float* b        = (const float*)d_in[5];
    const float* theta_b  = (const float*)d_in[7];
    const float* gcn_w    = (const float*)d_in[8];
    const float* gcn_b    = (const float*)d_in[9];
    const float* bn_gamma = (const float*)d_in[10];
    const float* bn_beta  = (const float*)d_in[11];
    const float* bn_mean  = (const float*)d_in[12];
    const float* bn_var   = (const float*)d_in[13];
    const float* lin_w    = (const float*)d_in[14];
    const float* lin_b    = (const float*)d_in[15];
    float* out = (float*)d_out;

    const int* src = ei;
    const int* dst = ei + N_EDGES;

    const int SM3 = 8704 * 4 * 4;  // 139264 B
    const int SM1 = 8704 * 2 * 4;  //  69632 B

    static cudaStream_t s1 = nullptr;
    static cudaEvent_t evRoot, evCnt, evH0, evG0;
    if (!s1) {
        cudaStreamCreateWithFlags(&s1, cudaStreamNonBlocking);
        cudaEventCreateWithFlags(&evRoot, cudaEventDisableTiming);
        cudaEventCreateWithFlags(&evCnt,  cudaEventDisableTiming);
        cudaEventCreateWithFlags(&evH0,   cudaEventDisableTiming);
        cudaEventCreateWithFlags(&evG0,   cudaEventDisableTiming);
        cudaFuncSetAttribute((const void*)gemm_tc<3, 0>,
                             cudaFuncAttributeMaxDynamicSharedMemorySize, SM3);
        cudaFuncSetAttribute((const void*)gemm_tc<1, 1>,
                             cudaFuncAttributeMaxDynamicSharedMemorySize, SM1);
    }

    float *hsp, *hhp;
    uint32_t* wcp;
    int* idp;
    cudaGetSymbolAddress((void**)&hsp, g_Hs);
    cudaGetSymbolAddress((void**)&hhp, g_hh);
    cudaGetSymbolAddress((void**)&wcp, g_Wc);
    cudaGetSymbolAddress((void**)&idp, g_indeg);

    const int M0 = 25088;                 // 196 tiles
    const int M1 = N_NODES - M0;          // 24912 -> 195 tiles
    const int mb1 = (M1 + 127) / 128;

    // fork
    cudaEventRecord(evRoot, 0);
    cudaStreamWaitEvent(s1, evRoot, 0);

    // ---- branch B (s1): CSR build ----
    init_kernel<<<(N_NODES + 255) / 256, 256, 0, s1>>>();
    count_kernel<<<(N_EDGES + 255) / 256, 256, 0, s1>>>(dst);
    cudaEventRecord(evCnt, s1);
    scan_a<<<NB, 256, 0, s1>>>();
    scan_b<<<1, 256, 0, s1>>>();
    scan_c<<<NB, 256, 0, s1>>>();
    fill_kernel<<<(N_EDGES + 255) / 256, 256, 0, s1>>>(src, dst);

    // ---- branch A (main): prep + gate GEMM halves ----
    prep_all<<<257, 256>>>(W_x, gcn_w, theta_b, b, w_c,
                           bn_gamma, bn_beta, bn_mean, bn_var, lin_w, lin_b);
    gemm_tc<3, 0><<<196, 512, SM3>>>(x, wcp, wcp + 16384, wcp + 2 * 16384,
                                     hsp, M0, nullptr);
    cudaEventRecord(evH0, 0);
    gemm_tc<3, 0><<<mb1, 512, SM3>>>(x + (size_t)M0 * 128, wcp, wcp + 16384,
                                     wcp + 2 * 16384, hsp + (size_t)M0 * 128, M1, nullptr);

    // s1: gemm1 half0 overlaps gemm3 half1
    cudaStreamWaitEvent(s1, evH0, 0);
    gemm_tc<1, 1><<<196, 512, SM1, s1>>>(hsp, wcp + 3 * 16384, nullptr, nullptr,
                                         hhp, M0, idp);
    cudaEventRecord(evG0, s1);

    // main: gemm1 half1 (needs indeg from count)
    cudaStreamWaitEvent(0, evCnt, 0);
    gemm_tc<1, 1><<<mb1, 512, SM1>>>(hsp + (size_t)M0 * 128, wcp + 3 * 16384,
                                     nullptr, nullptr, hhp + (size_t)M0 * 128, M1, idp + M0);

    // join: gather needs both gemm1 halves + CSR (evG0 is ordered after fill on s1)
    cudaStreamWaitEvent(0, evG0, 0);
    gather_finalize<<<(N_NODES * 32 + 255) / 256, 256>>>(gcn_b, out);
}

// round 7
// speedup vs baseline: 3.4936x; 1.1968x over previous
#include <cuda_runtime.h>
#include <cstdint>
#include <math.h>

#define N_NODES 50000
#define N_EDGES 640000
#define NH (N_NODES * 128)
#define NB 196  // ceil(N_NODES / 256)

// ---------------- scratch (static device globals) ---------------------------
__device__ float g_hh[NH];            // Hs @ gcn_w (unscaled)
__device__ uint32_t g_Wc[4 * 16384];  // tf32 weights: gate i, c, o, gcn_w
__device__ int   g_indeg[N_NODES];
__device__ float g_dg[N_NODES];       // rsqrt(1 + indeg)
__device__ int   g_off[N_NODES + 1];
__device__ int   g_cursor[N_NODES];
__device__ int   g_csr[N_EDGES];
__device__ int   g_part[256];
// fused per-channel constants
__device__ float g_cb0[128], g_cb1[128], g_cb2[128], g_wc2[128];
__device__ float g_fa[128];
__device__ float g_fc;

// ---------------- helpers ----------------------------------------------------
__device__ __forceinline__ float tanhfast(float x) {
    float r; asm("tanh.approx.f32 %0, %1;" : "=f"(r) : "f"(x)); return r;
}
__device__ __forceinline__ float sigfast(float x) {
    return 0.5f * tanhfast(0.5f * x) + 0.5f;
}
__device__ __forceinline__ uint32_t to_tf32(float x) {
    uint32_t u; asm("cvt.rna.tf32.f32 %0, %1;" : "=r"(u) : "f"(x)); return u;
}
__device__ __forceinline__ void mma_tf32(float* d, const uint32_t* a, uint32_t b0, uint32_t b1) {
    asm volatile(
        "mma.sync.aligned.m16n8k8.row.col.f32.tf32.tf32.f32 "
        "{%0,%1,%2,%3}, {%4,%5,%6,%7}, {%8,%9}, {%0,%1,%2,%3};"
        : "+f"(d[0]), "+f"(d[1]), "+f"(d[2]), "+f"(d[3])
        : "r"(a[0]), "r"(a[1]), "r"(a[2]), "r"(a[3]), "r"(b0), "r"(b1));
}
__device__ __forceinline__ uint32_t smem_u32(const void* p) {
    uint32_t a;
    asm("{ .reg .u64 t; cvta.to.shared.u64 t, %1; cvt.u32.u64 %0, t; }" : "=r"(a) : "l"(p));
    return a;
}
__device__ __forceinline__ void cp_async16(uint32_t daddr, const void* saddr, int srcsz) {
    asm volatile("cp.async.cg.shared.global [%0], [%1], 16, %2;"
                 :: "r"(daddr), "l"(saddr), "r"(srcsz) : "memory");
}

// ---------------- fused prep: weights->tf32 + per-channel constants ----------
__global__ void prep_all(const float* __restrict__ Wx, const float* __restrict__ gcn,
                         const float* __restrict__ theta_b, const float* __restrict__ b,
                         const float* __restrict__ w_c,
                         const float* __restrict__ gamma, const float* __restrict__ beta,
                         const float* __restrict__ mean, const float* __restrict__ var,
                         const float* __restrict__ lin_w, const float* __restrict__ lin_b) {
    if (blockIdx.x < 256) {
        int i = blockIdx.x * 256 + threadIdx.x;   // 0..65535
        int m = i >> 14, r = i & 16383;
        const float* S = (m == 0) ? Wx
                       : (m == 1) ? Wx + 2 * 16384
                       : (m == 2) ? Wx + 3 * 16384 : gcn;
        g_Wc[i] = to_tf32(S[r]);
        return;
    }
    int ch = threadIdx.x;
    if (ch >= 128) return;
    g_cb0[ch] = theta_b[ch] + b[ch];
    g_cb1[ch] = theta_b[256 + ch] + b[256 + ch];
    g_cb2[ch] = theta_b[384 + ch] + b[384 + ch];
    g_wc2[ch] = w_c[256 + ch];
    float sc = gamma[ch] * rsqrtf(var[ch] + 1e-5f);
    g_fa[ch] = sc * lin_w[ch];
    __shared__ float red[128];
    red[ch] = (beta[ch] - mean[ch] * sc) * lin_w[ch];
    __syncthreads();
    for (int o = 64; o > 0; o >>= 1) { if (ch < o) red[ch] += red[ch + o]; __syncthreads(); }
    if (ch == 0) g_fc = red[0] + lin_b[0];
}

__global__ void init_kernel() {
    int i = blockIdx.x * blockDim.x + threadIdx.x;
    if (i < N_NODES) g_indeg[i] = 0;
}
__global__ void count_kernel(const int* __restrict__ dst) {
    int e = blockIdx.x * blockDim.x + threadIdx.x;
    if (e < N_EDGES) atomicAdd(&g_indeg[dst[e]], 1);
}

// ---- scan stage A: per-block partial sums ----
__global__ __launch_bounds__(256) void scan_a() {
    int i = blockIdx.x * 256 + threadIdx.x;
    int v = (i < N_NODES) ? g_indeg[i] : 0;
    int lane = threadIdx.x & 31, warp = threadIdx.x >> 5;
#pragma unroll
    for (int o = 16; o > 0; o >>= 1) v += __shfl_down_sync(0xffffffffu, v, o);
    __shared__ int ws[8];
    if (lane == 0) ws[warp] = v;
    __syncthreads();
    if (threadIdx.x == 0) {
        int s = 0;
#pragma unroll
        for (int w = 0; w < 8; w++) s += ws[w];
        g_part[blockIdx.x] = s;
    }
}
// ---- scan stage BC: every block re-scans the partials (784B) + local scan ----
__global__ __launch_bounds__(256) void scan_bc() {
    int t = threadIdx.x, lane = t & 31, warp = t >> 5;
    __shared__ int s2[256];
    __shared__ int ws[8];
    // inclusive scan of partials
    {
        int v = (t < NB) ? g_part[t] : 0;
        int x = v;
#pragma unroll
        for (int o = 1; o < 32; o <<= 1) {
            int y = __shfl_up_sync(0xffffffffu, x, o);
            if (lane >= o) x += y;
        }
        if (lane == 31) ws[warp] = x;
        __syncthreads();
        if (warp == 0 && lane < 8) {
            int w = ws[lane];
#pragma unroll
            for (int o = 1; o < 8; o <<= 1) {
                int y = __shfl_up_sync(0xffu, w, o);
                if (lane >= o) w += y;
            }
            ws[lane] = w;
        }
        __syncthreads();
        s2[t] = x + (warp > 0 ? ws[warp - 1] : 0);
        __syncthreads();
    }
    int blockbase = (blockIdx.x == 0) ? 0 : s2[blockIdx.x - 1];
    __syncthreads();  // protect ws reuse
    // local exclusive scan over this block's 256 elements
    int i = blockIdx.x * 256 + t;
    int v = (i < N_NODES) ? g_indeg[i] : 0;
    int x = v;
#pragma unroll
    for (int o = 1; o < 32; o <<= 1) {
        int y = __shfl_up_sync(0xffffffffu, x, o);
        if (lane >= o) x += y;
    }
    if (lane == 31) ws[warp] = x;
    __syncthreads();
    if (warp == 0 && lane < 8) {
        int w = ws[lane];
#pragma unroll
        for (int o = 1; o < 8; o <<= 1) {
            int y = __shfl_up_sync(0xffu, w, o);
            if (lane >= o) w += y;
        }
        ws[lane] = w;
    }
    __syncthreads();
    if (i < N_NODES) {
        g_off[i] = x - v + (warp > 0 ? ws[warp - 1] : 0) + blockbase;
        g_dg[i] = rsqrtf(1.0f + (float)v);
        g_cursor[i] = 0;
    }
}

__global__ void fill_kernel(const int* __restrict__ src, const int* __restrict__ dst) {
    int e = blockIdx.x * blockDim.x + threadIdx.x;
    if (e >= N_EDGES) return;
    int d = dst[e];
    g_csr[g_off[d] + atomicAdd(&g_cursor[d], 1)] = src[e];
}

// ============================================================================
// Fully fused GEMM: gates (3x tf32 MMA) + LSTM -> Hs (smem only) -> Hs@gcn_w.
// 512 threads, 16 warps (4m x 4n), warp tile 32x32, K chunks of 64.
// smem u32 buffers (8704 each): [0]=A / Hs-c0, [1]=B_i / Hs-c1,
//                               [2]=B_c / gcnw-c0, [3]=B_o / gcnw-c1
// A layout pitch 68, B layout pitch 136.
// ============================================================================
__global__ __launch_bounds__(512, 1) void gemm_fused(
    const float* __restrict__ A, const uint32_t* __restrict__ W,
    float* __restrict__ out, int M)
{
    extern __shared__ uint32_t sm[];
    const int tid = threadIdx.x, lane = tid & 31;
    const int wid = tid >> 5, wm = wid >> 2, wn = wid & 3;
    const int q = lane >> 2, r = lane & 3;
    const int rowblk = blockIdx.x * 128;
    const uint32_t sbase = smem_u32(sm);

    float C[3][2][4][4];
#pragma unroll
    for (int g = 0; g < 3; g++)
#pragma unroll
        for (int i = 0; i < 2; i++)
#pragma unroll
            for (int j = 0; j < 4; j++)
#pragma unroll
                for (int k = 0; k < 4; k++) C[g][i][j][k] = 0.0f;

    // ================= phase 1: z = x @ W_gate for 3 gates =================
#pragma unroll
    for (int chunk = 0; chunk < 2; chunk++) {
        const int k0 = chunk * 64;
        if (chunk) __syncthreads();
        // B gates via cp.async
#pragma unroll
        for (int g = 0; g < 3; g++) {
#pragma unroll
            for (int t = 0; t < 4; t++) {
                int i = tid + t * 512;
                int row = i >> 5, j = i & 31;
                cp_async16(sbase + (8704 * (1 + g) + row * 136 + j * 4) * 4,
                           W + (size_t)g * 16384 + (size_t)(k0 + row) * 128 + j * 4, 16);
            }
        }
        asm volatile("cp.async.commit_group;" ::: "memory");
        // A via register+cvt (fp32 -> tf32 rna)
#pragma unroll
        for (int t = 0; t < 4; t++) {
            int i = tid + t * 512;
            int row = i >> 4, j = i & 15;
            int gr = rowblk + row;
            float4 v = make_float4(0.f, 0.f, 0.f, 0.f);
            if (gr < M) v = *(const float4*)(A + (size_t)gr * 128 + k0 + j * 4);
            uint32_t* p = &sm[row * 68 + j * 4];
            p[0] = to_tf32(v.x); p[1] = to_tf32(v.y);
            p[2] = to_tf32(v.z); p[3] = to_tf32(v.w);
        }
        asm volatile("cp.async.wait_group 0;" ::: "memory");
        __syncthreads();

#pragma unroll
        for (int ks = 0; ks < 8; ks++) {
            const int kb = ks * 8;
            uint32_t a[2][4];
#pragma unroll
            for (int ma = 0; ma < 2; ma++) {
                int m = wm * 32 + ma * 16 + q;
                const uint32_t* ap = &sm[m * 68 + kb + r];
                a[ma][0] = ap[0];
                a[ma][2] = ap[4];
                a[ma][1] = ap[8 * 68];
                a[ma][3] = ap[8 * 68 + 4];
            }
#pragma unroll
            for (int g = 0; g < 3; g++) {
                const uint32_t* bs = sm + 8704 * (1 + g);
#pragma unroll
                for (int na = 0; na < 4; na++) {
                    int n = wn * 32 + na * 8 + q;
                    const uint32_t* bp = &bs[(kb + r) * 136 + n];
                    uint32_t b0 = bp[0], b1 = bp[4 * 136];
#pragma unroll
                    for (int ma = 0; ma < 2; ma++) mma_tf32(C[g][ma][na], a[ma], b0, b1);
                }
            }
        }
    }
    __syncthreads();  // everyone done reading A/B before overwrite

    // kick off gcn_w loads into bufs 2,3 (overlaps LSTM epilogue math)
#pragma unroll
    for (int t = 0; t < 8; t++) {
        int i = tid + t * 512;              // 0..4095 over both chunks
        int chunk = i >> 11;                // 0/1
        int rj = i & 2047;
        int row = rj >> 5, j = rj & 31;
        cp_async16(sbase + (8704 * (2 + chunk) + row * 136 + j * 4) * 4,
                   W + 3 * 16384 + (size_t)(chunk * 64 + row) * 128 + j * 4, 16);
    }
    asm volatile("cp.async.commit_group;" ::: "memory");

    // ============ LSTM epilogue -> Hs (tf32 bits) into smem bufs 0,1 ========
#pragma unroll
    for (int ma = 0; ma < 2; ma++) {
#pragma unroll
        for (int half = 0; half < 2; half++) {
            int lrow = wm * 32 + ma * 16 + q + half * 8;   // 0..127 local row
#pragma unroll
            for (int na = 0; na < 4; na++) {
                int ch = wn * 32 + na * 8 + 2 * r;
                uint32_t h2[2];
#pragma unroll
                for (int e = 0; e < 2; e++) {
                    int c = ch + e;
                    float zi = C[0][ma][na][half * 2 + e] + g_cb0[c];
                    float zc = C[1][ma][na][half * 2 + e] + g_cb1[c];
                    float zo = C[2][ma][na][half * 2 + e] + g_cb2[c];
                    float I = sigfast(zi);
                    float T = tanhfast(zc);
                    float Cs = I * T;
                    float O = sigfast(zo + g_wc2[c] * Cs);
                    h2[e] = to_tf32(O * tanhfast(Cs));
                }
                int cchunk = ch >> 6, col = ch & 63;
                uint32_t* p = &sm[cchunk * 8704 + lrow * 68 + col];
                p[0] = h2[0]; p[1] = h2[1];
            }
        }
    }
    asm volatile("cp.async.wait_group 0;" ::: "memory");
    __syncthreads();

    // ================= phase 2: hh = Hs @ gcn_w =============================
    float D[2][4][4];
#pragma unroll
    for (int i = 0; i < 2; i++)
#pragma unroll
        for (int j = 0; j < 4; j++)
#pragma unroll
            for (int k = 0; k < 4; k++) D[i][j][k] = 0.0f;

#pragma unroll
    for (int chunk = 0; chunk < 2; chunk++) {
        const uint32_t* as = sm + chunk * 8704;
        const uint32_t* bs = sm + (2 + chunk) * 8704;
#pragma unroll
        for (int ks = 0; ks < 8; ks++) {
            const int kb = ks * 8;
            uint32_t a[2][4];
#pragma unroll
            for (int ma = 0; ma < 2; ma++) {
                int m = wm * 32 + ma * 16 + q;
                const uint32_t* ap = &as[m * 68 + kb + r];
                a[ma][0] = ap[0];
                a[ma][2] = ap[4];
                a[ma][1] = ap[8 * 68];
                a[ma][3] = ap[8 * 68 + 4];
            }
#pragma unroll
            for (int na = 0; na < 4; na++) {
                int n = wn * 32 + na * 8 + q;
                const uint32_t* bp = &bs[(kb + r) * 136 + n];
                uint32_t b0 = bp[0], b1 = bp[4 * 136];
#pragma unroll
                for (int ma = 0; ma < 2; ma++) mma_tf32(D[ma][na], a[ma], b0, b1);
            }
        }
    }

    // ---- epilogue 2: write hh (unscaled) ----
#pragma unroll
    for (int ma = 0; ma < 2; ma++) {
#pragma unroll
        for (int half = 0; half < 2; half++) {
            int row = rowblk + wm * 32 + ma * 16 + q + half * 8;
            if (row >= M) continue;
#pragma unroll
            for (int na = 0; na < 4; na++) {
                int ch = wn * 32 + na * 8 + 2 * r;
                *(float2*)(out + (size_t)row * 128 + ch) =
                    make_float2(D[ma][na][half * 2], D[ma][na][half * 2 + 1]);
            }
        }
    }
}

// ============================================================================
// gather + finalize: warp per node
// g = relu(dg_i*(dg_i*h_i + sum_s dg_s*h_s) + gcn_b); out = sum g*fa + fc
// ============================================================================
__global__ __launch_bounds__(256) void gather_finalize(const float* __restrict__ gcn_b,
                                                       float* __restrict__ out)
{
    int node = (blockIdx.x * blockDim.x + threadIdx.x) >> 5;
    int lane = threadIdx.x & 31;
    if (node >= N_NODES) return;
    int cnt = g_indeg[node];
    int base = g_off[node];
    float dgi = g_dg[node];

    const float4* hh4 = (const float4*)g_hh;
    float4 h = hh4[(size_t)node * 32 + lane];
    float4 acc = make_float4(dgi * h.x, dgi * h.y, dgi * h.z, dgi * h.w);  // self
    for (int e0 = 0; e0 < cnt; e0 += 32) {
        int myidx = (e0 + lane < cnt) ? g_csr[base + e0 + lane] : 0;
        int lim = min(32, cnt - e0);
        for (int t = 0; t < lim; t++) {
            int s = __shfl_sync(0xffffffffu, myidx, t);
            float ds = __ldg(g_dg + s);
            float4 v = __ldg(hh4 + (size_t)s * 32 + lane);
            acc.x = fmaf(ds, v.x, acc.x);
            acc.y = fmaf(ds, v.y, acc.y);
            acc.z = fmaf(ds, v.z, acc.z);
            acc.w = fmaf(ds, v.w, acc.w);
        }
    }

    float4 gb = ((const float4*)gcn_b)[lane];
    float4 fa = ((const float4*)g_fa)[lane];
    float sum = fmaxf(dgi * acc.x + gb.x, 0.0f) * fa.x
              + fmaxf(dgi * acc.y + gb.y, 0.0f) * fa.y
              + fmaxf(dgi * acc.z + gb.z, 0.0f) * fa.z
              + fmaxf(dgi * acc.w + gb.w, 0.0f) * fa.w;
#pragma unroll
    for (int o = 16; o > 0; o >>= 1) sum += __shfl_down_sync(0xffffffffu, sum, o);
    if (lane == 0) out[node] = sum + g_fc;
}

// ============================================================================
// launch: main = prep -> fused gemm -> gather ; s1 = CSR build
// ============================================================================
extern "C" void kernel_launch(void* const* d_in, const int* in_sizes, int n_in,
                              void* d_out, int out_size)
{
    const float* x        = (const float*)d_in[0];
    const int*   ei       = (const int*)  d_in[1];
    const float* W_x      = (const float*)d_in[3];
    const float* w_c      = (const float*)d_in[4];
    const float* b        = (const float*)d_in[5];
    const float* theta_b  = (const float*)d_in[7];
    const float* gcn_w    = (const float*)d_in[8];
    const float* gcn_b    = (const float*)d_in[9];
    const float* bn_gamma = (const float*)d_in[10];
    const float* bn_beta  = (const float*)d_in[11];
    const float* bn_mean  = (const float*)d_in[12];
    const float* bn_var   = (const float*)d_in[13];
    const float* lin_w    = (const float*)d_in[14];
    const float* lin_b    = (const float*)d_in[15];
    float* out = (float*)d_out;

    const int* src = ei;
    const int* dst = ei + N_EDGES;

    const int SMF = 8704 * 4 * 4;  // 139264 B

    static cudaStream_t s1 = nullptr;
    static cudaEvent_t evRoot, evCsr;
    if (!s1) {
        cudaStreamCreateWithFlags(&s1, cudaStreamNonBlocking);
        cudaEventCreateWithFlags(&evRoot, cudaEventDisableTiming);
        cudaEventCreateWithFlags(&evCsr,  cudaEventDisableTiming);
        cudaFuncSetAttribute((const void*)gemm_fused,
                             cudaFuncAttributeMaxDynamicSharedMemorySize, SMF);
    }

    float* hhp;
    uint32_t* wcp;
    cudaGetSymbolAddress((void**)&hhp, g_hh);
    cudaGetSymbolAddress((void**)&wcp, g_Wc);

    // fork
    cudaEventRecord(evRoot, 0);
    cudaStreamWaitEvent(s1, evRoot, 0);

    // ---- branch B (s1): CSR build ----
    init_kernel<<<(N_NODES + 255) / 256, 256, 0, s1>>>();
    count_kernel<<<(N_EDGES + 255) / 256, 256, 0, s1>>>(dst);
    scan_a<<<NB, 256, 0, s1>>>();
    scan_bc<<<NB, 256, 0, s1>>>();
    fill_kernel<<<(N_EDGES + 255) / 256, 256, 0, s1>>>(src, dst);
    cudaEventRecord(evCsr, s1);

    // ---- branch A (main): prep + fully fused GEMM ----
    prep_all<<<257, 256>>>(W_x, gcn_w, theta_b, b, w_c,
                           bn_gamma, bn_beta, bn_mean, bn_var, lin_w, lin_b);
    gemm_fused<<<(N_NODES + 127) / 128, 512, SMF>>>(x, wcp, hhp, N_NODES);

    // join
    cudaStreamWaitEvent(0, evCsr, 0);
    gather_finalize<<<(N_NODES * 32 + 255) / 256, 256>>>(gcn_b, out);
}

// round 8
// speedup vs baseline: 3.6047x; 1.0318x over previous
#include <cuda_runtime.h>
#include <cstdint>
#include <math.h>

#define N_NODES 50000
#define N_EDGES 640000
#define NH (N_NODES * 128)
#define NB 196  // ceil(N_NODES / 256)

// ---------------- scratch (static device globals) ---------------------------
__device__ uint32_t g_hhb[NH / 2];    // Hs @ gcn_w (unscaled), bf16x2 packed
__device__ uint32_t g_Wc[4 * 16384];  // tf32 weights: gate i, c, o, gcn_w
__device__ int   g_indeg[N_NODES];
__device__ float g_dg[N_NODES];       // rsqrt(1 + indeg)
__device__ int   g_off[N_NODES + 1];
__device__ int   g_cursor[N_NODES];
__device__ int   g_csr[N_EDGES];
__device__ int   g_part[256];
// fused per-channel constants
__device__ float g_cb0[128], g_cb1[128], g_cb2[128], g_wc2[128];
__device__ float g_fa[128];
__device__ float g_fc;

// ---------------- helpers ----------------------------------------------------
__device__ __forceinline__ float tanhfast(float x) {
    float r; asm("tanh.approx.f32 %0, %1;" : "=f"(r) : "f"(x)); return r;
}
__device__ __forceinline__ float sigfast(float x) {
    return 0.5f * tanhfast(0.5f * x) + 0.5f;
}
__device__ __forceinline__ uint32_t to_tf32(float x) {
    uint32_t u; asm("cvt.rna.tf32.f32 %0, %1;" : "=r"(u) : "f"(x)); return u;
}
// pack: hi -> upper 16, lo -> lower 16 (round-to-nearest-even)
__device__ __forceinline__ uint32_t pack_bf16x2(float hi, float lo) {
    uint32_t u; asm("cvt.rn.bf16x2.f32 %0, %1, %2;" : "=r"(u) : "f"(hi), "f"(lo)); return u;
}
__device__ __forceinline__ float bf_lo(uint32_t u) { return __uint_as_float(u << 16); }
__device__ __forceinline__ float bf_hi(uint32_t u) { return __uint_as_float(u & 0xffff0000u); }
__device__ __forceinline__ void mma_tf32(float* d, const uint32_t* a, uint32_t b0, uint32_t b1) {
    asm volatile(
        "mma.sync.aligned.m16n8k8.row.col.f32.tf32.tf32.f32 "
        "{%0,%1,%2,%3}, {%4,%5,%6,%7}, {%8,%9}, {%0,%1,%2,%3};"
        : "+f"(d[0]), "+f"(d[1]), "+f"(d[2]), "+f"(d[3])
        : "r"(a[0]), "r"(a[1]), "r"(a[2]), "r"(a[3]), "r"(b0), "r"(b1));
}
__device__ __forceinline__ uint32_t smem_u32(const void* p) {
    uint32_t a;
    asm("{ .reg .u64 t; cvta.to.shared.u64 t, %1; cvt.u32.u64 %0, t; }" : "=r"(a) : "l"(p));
    return a;
}
__device__ __forceinline__ void cp_async16(uint32_t daddr, const void* saddr, int srcsz) {
    asm volatile("cp.async.cg.shared.global [%0], [%1], 16, %2;"
                 :: "r"(daddr), "l"(saddr), "r"(srcsz) : "memory");
}

// ---------------- fused prep: weights->tf32 + per-channel constants ----------
__global__ void prep_all(const float* __restrict__ Wx, const float* __restrict__ gcn,
                         const float* __restrict__ theta_b, const float* __restrict__ b,
                         const float* __restrict__ w_c,
                         const float* __restrict__ gamma, const float* __restrict__ beta,
                         const float* __restrict__ mean, const float* __restrict__ var,
                         const float* __restrict__ lin_w, const float* __restrict__ lin_b) {
    if (blockIdx.x < 256) {
        int i = blockIdx.x * 256 + threadIdx.x;   // 0..65535
        int m = i >> 14, r = i & 16383;
        const float* S = (m == 0) ? Wx
                       : (m == 1) ? Wx + 2 * 16384
                       : (m == 2) ? Wx + 3 * 16384 : gcn;
        g_Wc[i] = to_tf32(S[r]);
        return;
    }
    int ch = threadIdx.x;
    if (ch >= 128) return;
    g_cb0[ch] = theta_b[ch] + b[ch];
    g_cb1[ch] = theta_b[256 + ch] + b[256 + ch];
    g_cb2[ch] = theta_b[384 + ch] + b[384 + ch];
    g_wc2[ch] = w_c[256 + ch];
    float sc = gamma[ch] * rsqrtf(var[ch] + 1e-5f);
    g_fa[ch] = sc * lin_w[ch];
    __shared__ float red[128];
    red[ch] = (beta[ch] - mean[ch] * sc) * lin_w[ch];
    __syncthreads();
    for (int o = 64; o > 0; o >>= 1) { if (ch < o) red[ch] += red[ch + o]; __syncthreads(); }
    if (ch == 0) g_fc = red[0] + lin_b[0];
}

__global__ void init_kernel() {
    int i = blockIdx.x * blockDim.x + threadIdx.x;
    if (i < N_NODES) g_indeg[i] = 0;
}
__global__ void count_kernel(const int* __restrict__ dst) {
    int e = blockIdx.x * blockDim.x + threadIdx.x;
    if (e < N_EDGES) atomicAdd(&g_indeg[dst[e]], 1);
}

// ---- scan stage A: per-block partial sums ----
__global__ __launch_bounds__(256) void scan_a() {
    int i = blockIdx.x * 256 + threadIdx.x;
    int v = (i < N_NODES) ? g_indeg[i] : 0;
    int lane = threadIdx.x & 31, warp = threadIdx.x >> 5;
#pragma unroll
    for (int o = 16; o > 0; o >>= 1) v += __shfl_down_sync(0xffffffffu, v, o);
    __shared__ int ws[8];
    if (lane == 0) ws[warp] = v;
    __syncthreads();
    if (threadIdx.x == 0) {
        int s = 0;
#pragma unroll
        for (int w = 0; w < 8; w++) s += ws[w];
        g_part[blockIdx.x] = s;
    }
}
// ---- scan stage BC: every block re-scans partials (784B) + local scan ----
__global__ __launch_bounds__(256) void scan_bc() {
    int t = threadIdx.x, lane = t & 31, warp = t >> 5;
    __shared__ int s2[256];
    __shared__ int ws[8];
    {
        int v = (t < NB) ? g_part[t] : 0;
        int x = v;
#pragma unroll
        for (int o = 1; o < 32; o <<= 1) {
            int y = __shfl_up_sync(0xffffffffu, x, o);
            if (lane >= o) x += y;
        }
        if (lane == 31) ws[warp] = x;
        __syncthreads();
        if (warp == 0 && lane < 8) {
            int w = ws[lane];
#pragma unroll
            for (int o = 1; o < 8; o <<= 1) {
                int y = __shfl_up_sync(0xffu, w, o);
                if (lane >= o) w += y;
            }
            ws[lane] = w;
        }
        __syncthreads();
        s2[t] = x + (warp > 0 ? ws[warp - 1] : 0);
        __syncthreads();
    }
    int blockbase = (blockIdx.x == 0) ? 0 : s2[blockIdx.x - 1];
    __syncthreads();
    int i = blockIdx.x * 256 + t;
    int v = (i < N_NODES) ? g_indeg[i] : 0;
    int x = v;
#pragma unroll
    for (int o = 1; o < 32; o <<= 1) {
        int y = __shfl_up_sync(0xffffffffu, x, o);
        if (lane >= o) x += y;
    }
    if (lane == 31) ws[warp] = x;
    __syncthreads();
    if (warp == 0 && lane < 8) {
        int w = ws[lane];
#pragma unroll
        for (int o = 1; o < 8; o <<= 1) {
            int y = __shfl_up_sync(0xffu, w, o);
            if (lane >= o) w += y;
        }
        ws[lane] = w;
    }
    __syncthreads();
    if (i < N_NODES) {
        g_off[i] = x - v + (warp > 0 ? ws[warp - 1] : 0) + blockbase;
        g_dg[i] = rsqrtf(1.0f + (float)v);
        g_cursor[i] = 0;
    }
}

__global__ void fill_kernel(const int* __restrict__ src, const int* __restrict__ dst) {
    int e = blockIdx.x * blockDim.x + threadIdx.x;
    if (e >= N_EDGES) return;
    int d = dst[e];
    g_csr[g_off[d] + atomicAdd(&g_cursor[d], 1)] = src[e];
}

// ============================================================================
// Fully fused GEMM: gates (3x tf32 MMA) + LSTM -> Hs (smem only) -> Hs@gcn_w
// -> bf16x2 packed hh.  512 threads, 16 warps (4m x 4n), warp tile 32x32.
// ============================================================================
__global__ __launch_bounds__(512, 1) void gemm_fused(
    const float* __restrict__ A, const uint32_t* __restrict__ W,
    uint32_t* __restrict__ out, int M)
{
    extern __shared__ uint32_t sm[];
    const int tid = threadIdx.x, lane = tid & 31;
    const int wid = tid >> 5, wm = wid >> 2, wn = wid & 3;
    const int q = lane >> 2, r = lane & 3;
    const int rowblk = blockIdx.x * 128;
    const uint32_t sbase = smem_u32(sm);

    float C[3][2][4][4];
#pragma unroll
    for (int g = 0; g < 3; g++)
#pragma unroll
        for (int i = 0; i < 2; i++)
#pragma unroll
            for (int j = 0; j < 4; j++)
#pragma unroll
                for (int k = 0; k < 4; k++) C[g][i][j][k] = 0.0f;

    // ================= phase 1: z = x @ W_gate for 3 gates =================
#pragma unroll
    for (int chunk = 0; chunk < 2; chunk++) {
        const int k0 = chunk * 64;
        if (chunk) __syncthreads();
#pragma unroll
        for (int g = 0; g < 3; g++) {
#pragma unroll
            for (int t = 0; t < 4; t++) {
                int i = tid + t * 512;
                int row = i >> 5, j = i & 31;
                cp_async16(sbase + (8704 * (1 + g) + row * 136 + j * 4) * 4,
                           W + (size_t)g * 16384 + (size_t)(k0 + row) * 128 + j * 4, 16);
            }
        }
        asm volatile("cp.async.commit_group;" ::: "memory");
#pragma unroll
        for (int t = 0; t < 4; t++) {
            int i = tid + t * 512;
            int row = i >> 4, j = i & 15;
            int gr = rowblk + row;
            float4 v = make_float4(0.f, 0.f, 0.f, 0.f);
            if (gr < M) v = *(const float4*)(A + (size_t)gr * 128 + k0 + j * 4);
            uint32_t* p = &sm[row * 68 + j * 4];
            p[0] = to_tf32(v.x); p[1] = to_tf32(v.y);
            p[2] = to_tf32(v.z); p[3] = to_tf32(v.w);
        }
        asm volatile("cp.async.wait_group 0;" ::: "memory");
        __syncthreads();

#pragma unroll
        for (int ks = 0; ks < 8; ks++) {
            const int kb = ks * 8;
            uint32_t a[2][4];
#pragma unroll
            for (int ma = 0; ma < 2; ma++) {
                int m = wm * 32 + ma * 16 + q;
                const uint32_t* ap = &sm[m * 68 + kb + r];
                a[ma][0] = ap[0];
                a[ma][2] = ap[4];
                a[ma][1] = ap[8 * 68];
                a[ma][3] = ap[8 * 68 + 4];
            }
#pragma unroll
            for (int g = 0; g < 3; g++) {
                const uint32_t* bs = sm + 8704 * (1 + g);
#pragma unroll
                for (int na = 0; na < 4; na++) {
                    int n = wn * 32 + na * 8 + q;
                    const uint32_t* bp = &bs[(kb + r) * 136 + n];
                    uint32_t b0 = bp[0], b1 = bp[4 * 136];
#pragma unroll
                    for (int ma = 0; ma < 2; ma++) mma_tf32(C[g][ma][na], a[ma], b0, b1);
                }
            }
        }
    }
    __syncthreads();  // all reads of A/B done before overwrite

    // gcn_w loads into bufs 2,3 (overlap LSTM epilogue math)
#pragma unroll
    for (int t = 0; t < 8; t++) {
        int i = tid + t * 512;
        int chunk = i >> 11;
        int rj = i & 2047;
        int row = rj >> 5, j = rj & 31;
        cp_async16(sbase + (8704 * (2 + chunk) + row * 136 + j * 4) * 4,
                   W + 3 * 16384 + (size_t)(chunk * 64 + row) * 128 + j * 4, 16);
    }
    asm volatile("cp.async.commit_group;" ::: "memory");

    // ============ LSTM epilogue -> Hs (tf32 bits) into smem bufs 0,1 ========
#pragma unroll
    for (int ma = 0; ma < 2; ma++) {
#pragma unroll
        for (int half = 0; half < 2; half++) {
            int lrow = wm * 32 + ma * 16 + q + half * 8;
#pragma unroll
            for (int na = 0; na < 4; na++) {
                int ch = wn * 32 + na * 8 + 2 * r;
                uint32_t h2[2];
#pragma unroll
                for (int e = 0; e < 2; e++) {
                    int c = ch + e;
                    float zi = C[0][ma][na][half * 2 + e] + g_cb0[c];
                    float zc = C[1][ma][na][half * 2 + e] + g_cb1[c];
                    float zo = C[2][ma][na][half * 2 + e] + g_cb2[c];
                    float I = sigfast(zi);
                    float T = tanhfast(zc);
                    float Cs = I * T;
                    float O = sigfast(zo + g_wc2[c] * Cs);
                    h2[e] = to_tf32(O * tanhfast(Cs));
                }
                int cchunk = ch >> 6, col = ch & 63;
                uint32_t* p = &sm[cchunk * 8704 + lrow * 68 + col];
                p[0] = h2[0]; p[1] = h2[1];
            }
        }
    }
    asm volatile("cp.async.wait_group 0;" ::: "memory");
    __syncthreads();

    // ================= phase 2: hh = Hs @ gcn_w =============================
    float D[2][4][4];
#pragma unroll
    for (int i = 0; i < 2; i++)
#pragma unroll
        for (int j = 0; j < 4; j++)
#pragma unroll
            for (int k = 0; k < 4; k++) D[i][j][k] = 0.0f;

#pragma unroll
    for (int chunk = 0; chunk < 2; chunk++) {
        const uint32_t* as = sm + chunk * 8704;
        const uint32_t* bs = sm + (2 + chunk) * 8704;
#pragma unroll
        for (int ks = 0; ks < 8; ks++) {
            const int kb = ks * 8;
            uint32_t a[2][4];
#pragma unroll
            for (int ma = 0; ma < 2; ma++) {
                int m = wm * 32 + ma * 16 + q;
                const uint32_t* ap = &as[m * 68 + kb + r];
                a[ma][0] = ap[0];
                a[ma][2] = ap[4];
                a[ma][1] = ap[8 * 68];
                a[ma][3] = ap[8 * 68 + 4];
            }
#pragma unroll
            for (int na = 0; na < 4; na++) {
                int n = wn * 32 + na * 8 + q;
                const uint32_t* bp = &bs[(kb + r) * 136 + n];
                uint32_t b0 = bp[0], b1 = bp[4 * 136];
#pragma unroll
                for (int ma = 0; ma < 2; ma++) mma_tf32(D[ma][na], a[ma], b0, b1);
            }
        }
    }

    // ---- epilogue 2: write hh as bf16x2 (ch+1 high, ch low) ----
#pragma unroll
    for (int ma = 0; ma < 2; ma++) {
#pragma unroll
        for (int half = 0; half < 2; half++) {
            int row = rowblk + wm * 32 + ma * 16 + q + half * 8;
            if (row >= M) continue;
#pragma unroll
            for (int na = 0; na < 4; na++) {
                int ch = wn * 32 + na * 8 + 2 * r;
                out[(size_t)row * 64 + (ch >> 1)] =
                    pack_bf16x2(D[ma][na][half * 2 + 1], D[ma][na][half * 2]);
            }
        }
    }
}

// ============================================================================
// gather + finalize: warp per node, bf16 hh (uint2 per lane = 4 channels)
// g = relu(dg_i*(dg_i*h_i + sum_s dg_s*h_s) + gcn_b); out = sum g*fa + fc
// ============================================================================
__global__ __launch_bounds__(256) void gather_finalize(const float* __restrict__ gcn_b,
                                                       float* __restrict__ out)
{
    int node = (blockIdx.x * blockDim.x + threadIdx.x) >> 5;
    int lane = threadIdx.x & 31;
    if (node >= N_NODES) return;
    int cnt = g_indeg[node];
    int base = g_off[node];
    float dgi = g_dg[node];

    const uint2* hh2 = (const uint2*)g_hhb;
    uint2 hv = hh2[(size_t)node * 32 + lane];
    float a0 = dgi * bf_lo(hv.x), a1 = dgi * bf_hi(hv.x);
    float a2 = dgi * bf_lo(hv.y), a3 = dgi * bf_hi(hv.y);

    for (int e0 = 0; e0 < cnt; e0 += 32) {
        int myidx = (e0 + lane < cnt) ? g_csr[base + e0 + lane] : 0;
        int lim = min(32, cnt - e0);
        for (int t = 0; t < lim; t++) {
            int s = __shfl_sync(0xffffffffu, myidx, t);
            float ds = __ldg(g_dg + s);
            uint2 v = __ldg(hh2 + (size_t)s * 32 + lane);
            a0 = fmaf(ds, bf_lo(v.x), a0);
            a1 = fmaf(ds, bf_hi(v.x), a1);
            a2 = fmaf(ds, bf_lo(v.y), a2);
            a3 = fmaf(ds, bf_hi(v.y), a3);
        }
    }

    float4 gb = ((const float4*)gcn_b)[lane];
    float4 fa = ((const float4*)g_fa)[lane];
    float sum = fmaxf(dgi * a0 + gb.x, 0.0f) * fa.x
              + fmaxf(dgi * a1 + gb.y, 0.0f) * fa.y
              + fmaxf(dgi * a2 + gb.z, 0.0f) * fa.z
              + fmaxf(dgi * a3 + gb.w, 0.0f) * fa.w;
#pragma unroll
    for (int o = 16; o > 0; o >>= 1) sum += __shfl_down_sync(0xffffffffu, sum, o);
    if (lane == 0) out[node] = sum + g_fc;
}

// ============================================================================
// launch: main = prep -> fused gemm -> gather ; s1 = CSR build
// ============================================================================
extern "C" void kernel_launch(void* const* d_in, const int* in_sizes, int n_in,
                              void* d_out, int out_size)
{
    const float* x        = (const float*)d_in[0];
    const int*   ei       = (const int*)  d_in[1];
    const float* W_x      = (const float*)d_in[3];
    const float* w_c      = (const float*)d_in[4];
    const float* b        = (const float*)d_in[5];
    const float* theta_b  = (const float*)d_in[7];
    const float* gcn_w    = (const float*)d_in[8];
    const float* gcn_b    = (const float*)d_in[9];
    const float* bn_gamma = (const float*)d_in[10];
    const float* bn_beta  = (const float*)d_in[11];
    const float* bn_mean  = (const float*)d_in[12];
    const float* bn_var   = (const float*)d_in[13];
    const float* lin_w    = (const float*)d_in[14];
    const float* lin_b    = (const float*)d_in[15];
    float* out = (float*)d_out;

    const int* src = ei;
    const int* dst = ei + N_EDGES;

    const int SMF = 8704 * 4 * 4;  // 139264 B

    static cudaStream_t s1 = nullptr;
    static cudaEvent_t evRoot, evCsr;
    if (!s1) {
        cudaStreamCreateWithFlags(&s1, cudaStreamNonBlocking);
        cudaEventCreateWithFlags(&evRoot, cudaEventDisableTiming);
        cudaEventCreateWithFlags(&evCsr,  cudaEventDisableTiming);
        cudaFuncSetAttribute((const void*)gemm_fused,
                             cudaFuncAttributeMaxDynamicSharedMemorySize, SMF);
    }

    uint32_t *hhp, *wcp;
    cudaGetSymbolAddress((void**)&hhp, g_hhb);
    cudaGetSymbolAddress((void**)&wcp, g_Wc);

    // fork
    cudaEventRecord(evRoot, 0);
    cudaStreamWaitEvent(s1, evRoot, 0);

    // ---- branch B (s1): CSR build ----
    init_kernel<<<(N_NODES + 255) / 256, 256, 0, s1>>>();
    count_kernel<<<(N_EDGES + 255) / 256, 256, 0, s1>>>(dst);
    scan_a<<<NB, 256, 0, s1>>>();
    scan_bc<<<NB, 256, 0, s1>>>();
    fill_kernel<<<(N_EDGES + 255) / 256, 256, 0, s1>>>(src, dst);
    cudaEventRecord(evCsr, s1);

    // ---- branch A (main): prep + fully fused GEMM ----
    prep_all<<<257, 256>>>(W_x, gcn_w, theta_b, b, w_c,
                           bn_gamma, bn_beta, bn_mean, bn_var, lin_w, lin_b);
    gemm_fused<<<(N_NODES + 127) / 128, 512, SMF>>>(x, wcp, hhp, N_NODES);

    // join
    cudaStreamWaitEvent(0, evCsr, 0);
    gather_finalize<<<(N_NODES * 32 + 255) / 256, 256>>>(gcn_b, out);
}

// round 9
// speedup vs baseline: 3.6693x; 1.0179x over previous
#include <cuda_runtime.h>
#include <cstdint>
#include <math.h>

#define N_NODES 50000
#define N_EDGES 640000
#define NH (N_NODES * 128)
#define NB 196  // ceil(N_NODES / 256)

// ---------------- scratch (static device globals) ---------------------------
__device__ uint32_t g_hhb[NH / 2];    // Hs @ gcn_w (unscaled), bf16x2 packed
__device__ uint32_t g_Wc[4 * 16384];  // tf32 weights: gate i, c, o, gcn_w
__device__ int   g_indeg[N_NODES];
__device__ float g_dg[N_NODES];       // rsqrt(1 + indeg)
__device__ int   g_off[N_NODES + 1];
__device__ int   g_cursor[N_NODES];
__device__ int   g_csr[N_EDGES];
__device__ int   g_part[256];
// fused per-channel constants
__device__ float g_cb0[128], g_cb1[128], g_cb2[128], g_wc2[128];
__device__ float g_fa[128];
__device__ float g_fc;

// ---------------- helpers ----------------------------------------------------
__device__ __forceinline__ float tanhfast(float x) {
    float r; asm("tanh.approx.f32 %0, %1;" : "=f"(r) : "f"(x)); return r;
}
__device__ __forceinline__ float sigfast(float x) {
    return 0.5f * tanhfast(0.5f * x) + 0.5f;
}
__device__ __forceinline__ uint32_t to_tf32(float x) {
    uint32_t u; asm("cvt.rna.tf32.f32 %0, %1;" : "=r"(u) : "f"(x)); return u;
}
__device__ __forceinline__ uint32_t pack_bf16x2(float hi, float lo) {
    uint32_t u; asm("cvt.rn.bf16x2.f32 %0, %1, %2;" : "=r"(u) : "f"(hi), "f"(lo)); return u;
}
__device__ __forceinline__ float bf_lo(uint32_t u) { return __uint_as_float(u << 16); }
__device__ __forceinline__ float bf_hi(uint32_t u) { return __uint_as_float(u & 0xffff0000u); }
__device__ __forceinline__ void mma_tf32(float* d, const uint32_t* a, uint32_t b0, uint32_t b1) {
    asm volatile(
        "mma.sync.aligned.m16n8k8.row.col.f32.tf32.tf32.f32 "
        "{%0,%1,%2,%3}, {%4,%5,%6,%7}, {%8,%9}, {%0,%1,%2,%3};"
        : "+f"(d[0]), "+f"(d[1]), "+f"(d[2]), "+f"(d[3])
        : "r"(a[0]), "r"(a[1]), "r"(a[2]), "r"(a[3]), "r"(b0), "r"(b1));
}
__device__ __forceinline__ uint32_t smem_u32(const void* p) {
    uint32_t a;
    asm("{ .reg .u64 t; cvta.to.shared.u64 t, %1; cvt.u32.u64 %0, t; }" : "=r"(a) : "l"(p));
    return a;
}
__device__ __forceinline__ void cp_async16(uint32_t daddr, const void* saddr, int srcsz) {
    asm volatile("cp.async.cg.shared.global [%0], [%1], 16, %2;"
                 :: "r"(daddr), "l"(saddr), "r"(srcsz) : "memory");
}

// ---------------- prep: weights->tf32 + constants + indeg zero ---------------
__global__ void prep_all(const float* __restrict__ Wx, const float* __restrict__ gcn,
                         const float* __restrict__ theta_b, const float* __restrict__ b,
                         const float* __restrict__ w_c,
                         const float* __restrict__ gamma, const float* __restrict__ beta,
                         const float* __restrict__ mean, const float* __restrict__ var,
                         const float* __restrict__ lin_w, const float* __restrict__ lin_b) {
    if (blockIdx.x < 256) {
        int i = blockIdx.x * 256 + threadIdx.x;   // 0..65535
        int m = i >> 14, r = i & 16383;
        const float* S = (m == 0) ? Wx
                       : (m == 1) ? Wx + 2 * 16384
                       : (m == 2) ? Wx + 3 * 16384 : gcn;
        g_Wc[i] = to_tf32(S[r]);
        return;
    }
    if (blockIdx.x < 256 + NB) {
        int i = (blockIdx.x - 256) * 256 + threadIdx.x;
        if (i < N_NODES) g_indeg[i] = 0;
        return;
    }
    int ch = threadIdx.x;
    if (ch >= 128) return;
    g_cb0[ch] = theta_b[ch] + b[ch];
    g_cb1[ch] = theta_b[256 + ch] + b[256 + ch];
    g_cb2[ch] = theta_b[384 + ch] + b[384 + ch];
    g_wc2[ch] = w_c[256 + ch];
    float sc = gamma[ch] * rsqrtf(var[ch] + 1e-5f);
    g_fa[ch] = sc * lin_w[ch];
    __shared__ float red[128];
    red[ch] = (beta[ch] - mean[ch] * sc) * lin_w[ch];
    __syncthreads();
    for (int o = 64; o > 0; o >>= 1) { if (ch < o) red[ch] += red[ch + o]; __syncthreads(); }
    if (ch == 0) g_fc = red[0] + lin_b[0];
}

__global__ void count_kernel(const int* __restrict__ dst) {
    int e = blockIdx.x * blockDim.x + threadIdx.x;
    if (e < N_EDGES) atomicAdd(&g_indeg[dst[e]], 1);
}

// ---- scan stage A: per-block partial sums ----
__global__ __launch_bounds__(256) void scan_a() {
    int i = blockIdx.x * 256 + threadIdx.x;
    int v = (i < N_NODES) ? g_indeg[i] : 0;
    int lane = threadIdx.x & 31, warp = threadIdx.x >> 5;
#pragma unroll
    for (int o = 16; o > 0; o >>= 1) v += __shfl_down_sync(0xffffffffu, v, o);
    __shared__ int ws[8];
    if (lane == 0) ws[warp] = v;
    __syncthreads();
    if (threadIdx.x == 0) {
        int s = 0;
#pragma unroll
        for (int w = 0; w < 8; w++) s += ws[w];
        g_part[blockIdx.x] = s;
    }
}
// ---- scan stage BC: every block re-scans partials + local scan ----
__global__ __launch_bounds__(256) void scan_bc() {
    int t = threadIdx.x, lane = t & 31, warp = t >> 5;
    __shared__ int s2[256];
    __shared__ int ws[8];
    {
        int v = (t < NB) ? g_part[t] : 0;
        int x = v;
#pragma unroll
        for (int o = 1; o < 32; o <<= 1) {
            int y = __shfl_up_sync(0xffffffffu, x, o);
            if (lane >= o) x += y;
        }
        if (lane == 31) ws[warp] = x;
        __syncthreads();
        if (warp == 0 && lane < 8) {
            int w = ws[lane];
#pragma unroll
            for (int o = 1; o < 8; o <<= 1) {
                int y = __shfl_up_sync(0xffu, w, o);
                if (lane >= o) w += y;
            }
            ws[lane] = w;
        }
        __syncthreads();
        s2[t] = x + (warp > 0 ? ws[warp - 1] : 0);
        __syncthreads();
    }
    int blockbase = (blockIdx.x == 0) ? 0 : s2[blockIdx.x - 1];
    __syncthreads();
    int i = blockIdx.x * 256 + t;
    int v = (i < N_NODES) ? g_indeg[i] : 0;
    int x = v;
#pragma unroll
    for (int o = 1; o < 32; o <<= 1) {
        int y = __shfl_up_sync(0xffffffffu, x, o);
        if (lane >= o) x += y;
    }
    if (lane == 31) ws[warp] = x;
    __syncthreads();
    if (warp == 0 && lane < 8) {
        int w = ws[lane];
#pragma unroll
        for (int o = 1; o < 8; o <<= 1) {
            int y = __shfl_up_sync(0xffu, w, o);
            if (lane >= o) w += y;
        }
        ws[lane] = w;
    }
    __syncthreads();
    if (i < N_NODES) {
        g_off[i] = x - v + (warp > 0 ? ws[warp - 1] : 0) + blockbase;
        g_dg[i] = rsqrtf(1.0f + (float)v);
        g_cursor[i] = 0;
    }
}

__global__ void fill_kernel(const int* __restrict__ src, const int* __restrict__ dst) {
    int e = blockIdx.x * blockDim.x + threadIdx.x;
    if (e >= N_EDGES) return;
    int d = dst[e];
    g_csr[g_off[d] + atomicAdd(&g_cursor[d], 1)] = src[e];
}

// ============================================================================
// Fully fused GEMM: gates (3x tf32 MMA) + LSTM -> Hs (smem) -> Hs@gcn_w
// -> bf16x2 hh.  256 threads, 8 warps (2m x 4n), warp tile 64x32.
// smem u32 bufs (8704 each): [0]=A/Hs-c0, [1]=B_i/Hs-c1, [2]=B_c/gcnw-c0,
// [3]=B_o/gcnw-c1.  A pitch 68, B pitch 136.
// ============================================================================
__global__ __launch_bounds__(256, 1) void gemm_fused(
    const float* __restrict__ A, const uint32_t* __restrict__ W,
    uint32_t* __restrict__ out, int M)
{
    extern __shared__ uint32_t sm[];
    const int tid = threadIdx.x, lane = tid & 31;
    const int wid = tid >> 5, wm = wid >> 2, wn = wid & 3;
    const int q = lane >> 2, r = lane & 3;
    const int rowblk = blockIdx.x * 128;
    const uint32_t sbase = smem_u32(sm);

    float C[3][4][4][4];
#pragma unroll
    for (int g = 0; g < 3; g++)
#pragma unroll
        for (int i = 0; i < 4; i++)
#pragma unroll
            for (int j = 0; j < 4; j++)
#pragma unroll
                for (int k = 0; k < 4; k++) C[g][i][j][k] = 0.0f;

    // ================= phase 1: z = x @ W_gate for 3 gates =================
#pragma unroll
    for (int chunk = 0; chunk < 2; chunk++) {
        const int k0 = chunk * 64;
        if (chunk) __syncthreads();
#pragma unroll
        for (int g = 0; g < 3; g++) {
#pragma unroll
            for (int t = 0; t < 8; t++) {
                int i = tid + t * 256;
                int row = i >> 5, j = i & 31;
                cp_async16(sbase + (8704 * (1 + g) + row * 136 + j * 4) * 4,
                           W + (size_t)g * 16384 + (size_t)(k0 + row) * 128 + j * 4, 16);
            }
        }
        asm volatile("cp.async.commit_group;" ::: "memory");
#pragma unroll
        for (int t = 0; t < 8; t++) {
            int i = tid + t * 256;
            int row = i >> 4, j = i & 15;
            int gr = rowblk + row;
            float4 v = make_float4(0.f, 0.f, 0.f, 0.f);
            if (gr < M) v = *(const float4*)(A + (size_t)gr * 128 + k0 + j * 4);
            uint32_t* p = &sm[row * 68 + j * 4];
            p[0] = to_tf32(v.x); p[1] = to_tf32(v.y);
            p[2] = to_tf32(v.z); p[3] = to_tf32(v.w);
        }
        asm volatile("cp.async.wait_group 0;" ::: "memory");
        __syncthreads();

#pragma unroll
        for (int ks = 0; ks < 8; ks++) {
            const int kb = ks * 8;
            uint32_t a[4][4];
#pragma unroll
            for (int ma = 0; ma < 4; ma++) {
                int m = wm * 64 + ma * 16 + q;
                const uint32_t* ap = &sm[m * 68 + kb + r];
                a[ma][0] = ap[0];
                a[ma][2] = ap[4];
                a[ma][1] = ap[8 * 68];
                a[ma][3] = ap[8 * 68 + 4];
            }
#pragma unroll
            for (int g = 0; g < 3; g++) {
                const uint32_t* bs = sm + 8704 * (1 + g);
#pragma unroll
                for (int na = 0; na < 4; na++) {
                    int n = wn * 32 + na * 8 + q;
                    const uint32_t* bp = &bs[(kb + r) * 136 + n];
                    uint32_t b0 = bp[0], b1 = bp[4 * 136];
#pragma unroll
                    for (int ma = 0; ma < 4; ma++) mma_tf32(C[g][ma][na], a[ma], b0, b1);
                }
            }
        }
    }
    __syncthreads();  // all reads of A/B done before overwrite

    // gcn_w loads into bufs 2,3 (overlap LSTM epilogue math)
#pragma unroll
    for (int t = 0; t < 16; t++) {
        int i = tid + t * 256;
        int chunk = i >> 11;
        int rj = i & 2047;
        int row = rj >> 5, j = rj & 31;
        cp_async16(sbase + (8704 * (2 + chunk) + row * 136 + j * 4) * 4,
                   W + 3 * 16384 + (size_t)(chunk * 64 + row) * 128 + j * 4, 16);
    }
    asm volatile("cp.async.commit_group;" ::: "memory");

    // ============ LSTM epilogue -> Hs (tf32 bits) into smem bufs 0,1 ========
#pragma unroll
    for (int ma = 0; ma < 4; ma++) {
#pragma unroll
        for (int half = 0; half < 2; half++) {
            int lrow = wm * 64 + ma * 16 + q + half * 8;
#pragma unroll
            for (int na = 0; na < 4; na++) {
                int ch = wn * 32 + na * 8 + 2 * r;
                uint32_t h2[2];
#pragma unroll
                for (int e = 0; e < 2; e++) {
                    int c = ch + e;
                    float zi = C[0][ma][na][half * 2 + e] + g_cb0[c];
                    float zc = C[1][ma][na][half * 2 + e] + g_cb1[c];
                    float zo = C[2][ma][na][half * 2 + e] + g_cb2[c];
                    float I = sigfast(zi);
                    float T = tanhfast(zc);
                    float Cs = I * T;
                    float O = sigfast(zo + g_wc2[c] * Cs);
                    h2[e] = to_tf32(O * tanhfast(Cs));
                }
                int cchunk = ch >> 6, col = ch & 63;
                uint32_t* p = &sm[cchunk * 8704 + lrow * 68 + col];
                p[0] = h2[0]; p[1] = h2[1];
            }
        }
    }
    asm volatile("cp.async.wait_group 0;" ::: "memory");
    __syncthreads();

    // ================= phase 2: hh = Hs @ gcn_w =============================
    float D[4][4][4];
#pragma unroll
    for (int i = 0; i < 4; i++)
#pragma unroll
        for (int j = 0; j < 4; j++)
#pragma unroll
            for (int k = 0; k < 4; k++) D[i][j][k] = 0.0f;

#pragma unroll
    for (int chunk = 0; chunk < 2; chunk++) {
        const uint32_t* as = sm + chunk * 8704;
        const uint32_t* bs = sm + (2 + chunk) * 8704;
#pragma unroll
        for (int ks = 0; ks < 8; ks++) {
            const int kb = ks * 8;
            uint32_t a[4][4];
#pragma unroll
            for (int ma = 0; ma < 4; ma++) {
                int m = wm * 64 + ma * 16 + q;
                const uint32_t* ap = &as[m * 68 + kb + r];
                a[ma][0] = ap[0];
                a[ma][2] = ap[4];
                a[ma][1] = ap[8 * 68];
                a[ma][3] = ap[8 * 68 + 4];
            }
#pragma unroll
            for (int na = 0; na < 4; na++) {
                int n = wn * 32 + na * 8 + q;
                const uint32_t* bp = &bs[(kb + r) * 136 + n];
                uint32_t b0 = bp[0], b1 = bp[4 * 136];
#pragma unroll
                for (int ma = 0; ma < 4; ma++) mma_tf32(D[ma][na], a[ma], b0, b1);
            }
        }
    }

    // ---- epilogue 2: write hh as bf16x2 ----
#pragma unroll
    for (int ma = 0; ma < 4; ma++) {
#pragma unroll
        for (int half = 0; half < 2; half++) {
            int row = rowblk + wm * 64 + ma * 16 + q + half * 8;
            if (row >= M) continue;
#pragma unroll
            for (int na = 0; na < 4; na++) {
                int ch = wn * 32 + na * 8 + 2 * r;
                out[(size_t)row * 64 + (ch >> 1)] =
                    pack_bf16x2(D[ma][na][half * 2 + 1], D[ma][na][half * 2]);
            }
        }
    }
}

// ============================================================================
// gather + finalize: warp per node, bf16 hh, unroll-by-4 for MLP
// ============================================================================
__global__ __launch_bounds__(256) void gather_finalize(const float* __restrict__ gcn_b,
                                                       float* __restrict__ out)
{
    int node = (blockIdx.x * blockDim.x + threadIdx.x) >> 5;
    int lane = threadIdx.x & 31;
    if (node >= N_NODES) return;
    int cnt = g_indeg[node];
    int base = g_off[node];
    float dgi = g_dg[node];

    const uint2* hh2 = (const uint2*)g_hhb;
    uint2 hv = hh2[(size_t)node * 32 + lane];
    float a0 = dgi * bf_lo(hv.x), a1 = dgi * bf_hi(hv.x);
    float a2 = dgi * bf_lo(hv.y), a3 = dgi * bf_hi(hv.y);

    for (int e0 = 0; e0 < cnt; e0 += 32) {
        int myidx = (e0 + lane < cnt) ? g_csr[base + e0 + lane] : 0;
        int lim = min(32, cnt - e0);
        int t = 0;
        for (; t + 4 <= lim; t += 4) {
            int s0 = __shfl_sync(0xffffffffu, myidx, t);
            int s1 = __shfl_sync(0xffffffffu, myidx, t + 1);
            int s2 = __shfl_sync(0xffffffffu, myidx, t + 2);
            int s3 = __shfl_sync(0xffffffffu, myidx, t + 3);
            float d0 = __ldg(g_dg + s0);
            float d1 = __ldg(g_dg + s1);
            float d2 = __ldg(g_dg + s2);
            float d3 = __ldg(g_dg + s3);
            uint2 v0 = __ldg(hh2 + (size_t)s0 * 32 + lane);
            uint2 v1 = __ldg(hh2 + (size_t)s1 * 32 + lane);
            uint2 v2 = __ldg(hh2 + (size_t)s2 * 32 + lane);
            uint2 v3 = __ldg(hh2 + (size_t)s3 * 32 + lane);
            a0 = fmaf(d0, bf_lo(v0.x), a0); a1 = fmaf(d0, bf_hi(v0.x), a1);
            a2 = fmaf(d0, bf_lo(v0.y), a2); a3 = fmaf(d0, bf_hi(v0.y), a3);
            a0 = fmaf(d1, bf_lo(v1.x), a0); a1 = fmaf(d1, bf_hi(v1.x), a1);
            a2 = fmaf(d1, bf_lo(v1.y), a2); a3 = fmaf(d1, bf_hi(v1.y), a3);
            a0 = fmaf(d2, bf_lo(v2.x), a0); a1 = fmaf(d2, bf_hi(v2.x), a1);
            a2 = fmaf(d2, bf_lo(v2.y), a2); a3 = fmaf(d2, bf_hi(v2.y), a3);
            a0 = fmaf(d3, bf_lo(v3.x), a0); a1 = fmaf(d3, bf_hi(v3.x), a1);
            a2 = fmaf(d3, bf_lo(v3.y), a2); a3 = fmaf(d3, bf_hi(v3.y), a3);
        }
        for (; t < lim; t++) {
            int s = __shfl_sync(0xffffffffu, myidx, t);
            float ds = __ldg(g_dg + s);
            uint2 v = __ldg(hh2 + (size_t)s * 32 + lane);
            a0 = fmaf(ds, bf_lo(v.x), a0);
            a1 = fmaf(ds, bf_hi(v.x), a1);
            a2 = fmaf(ds, bf_lo(v.y), a2);
            a3 = fmaf(ds, bf_hi(v.y), a3);
        }
    }

    float4 gb = ((const float4*)gcn_b)[lane];
    float4 fa = ((const float4*)g_fa)[lane];
    float sum = fmaxf(dgi * a0 + gb.x, 0.0f) * fa.x
              + fmaxf(dgi * a1 + gb.y, 0.0f) * fa.y
              + fmaxf(dgi * a2 + gb.z, 0.0f) * fa.z
              + fmaxf(dgi * a3 + gb.w, 0.0f) * fa.w;
#pragma unroll
    for (int o = 16; o > 0; o >>= 1) sum += __shfl_down_sync(0xffffffffu, sum, o);
    if (lane == 0) out[node] = sum + g_fc;
}

// ============================================================================
// launch: main = prep -> gemm -> gather ; s1 = count -> scans -> fill
// ============================================================================
extern "C" void kernel_launch(void* const* d_in, const int* in_sizes, int n_in,
                              void* d_out, int out_size)
{
    const float* x        = (const float*)d_in[0];
    const int*   ei       = (const int*)  d_in[1];
    const float* W_x      = (const float*)d_in[3];
    const float* w_c      = (const float*)d_in[4];
    const float* b        = (const float*)d_in[5];
    const float* theta_b  = (const float*)d_in[7];
    const float* gcn_w    = (const float*)d_in[8];
    const float* gcn_b    = (const float*)d_in[9];
    const float* bn_gamma = (const float*)d_in[10];
    const float* bn_beta  = (const float*)d_in[11];
    const float* bn_mean  = (const float*)d_in[12];
    const float* bn_var   = (const float*)d_in[13];
    const float* lin_w    = (const float*)d_in[14];
    const float* lin_b    = (const float*)d_in[15];
    float* out = (float*)d_out;

    const int* src = ei;
    const int* dst = ei + N_EDGES;

    const int SMF = 8704 * 4 * 4;  // 139264 B

    static cudaStream_t s1 = nullptr;
    static cudaEvent_t evPrep, evCsr;
    if (!s1) {
        cudaStreamCreateWithFlags(&s1, cudaStreamNonBlocking);
        cudaEventCreateWithFlags(&evPrep, cudaEventDisableTiming);
        cudaEventCreateWithFlags(&evCsr,  cudaEventDisableTiming);
        cudaFuncSetAttribute((const void*)gemm_fused,
                             cudaFuncAttributeMaxDynamicSharedMemorySize, SMF);
    }

    uint32_t *hhp, *wcp;
    cudaGetSymbolAddress((void**)&hhp, g_hhb);
    cudaGetSymbolAddress((void**)&wcp, g_Wc);

    // main: prep (also zeroes indeg)
    prep_all<<<256 + NB + 1, 256>>>(W_x, gcn_w, theta_b, b, w_c,
                                    bn_gamma, bn_beta, bn_mean, bn_var, lin_w, lin_b);
    cudaEventRecord(evPrep, 0);

    // s1: CSR build (count waits for indeg zeroing)
    cudaStreamWaitEvent(s1, evPrep, 0);
    count_kernel<<<(N_EDGES + 255) / 256, 256, 0, s1>>>(dst);
    scan_a<<<NB, 256, 0, s1>>>();
    scan_bc<<<NB, 256, 0, s1>>>();
    fill_kernel<<<(N_EDGES + 255) / 256, 256, 0, s1>>>(src, dst);
    cudaEventRecord(evCsr, s1);

    // main: fused GEMM
    gemm_fused<<<(N_NODES + 127) / 128, 256, SMF>>>(x, wcp, hhp, N_NODES);

    // join
    cudaStreamWaitEvent(0, evCsr, 0);
    gather_finalize<<<(N_NODES * 32 + 255) / 256, 256>>>(gcn_b, out);
}

// round 10
// speedup vs baseline: 3.6896x; 1.0055x over previous
#include <cuda_runtime.h>
#include <cstdint>
#include <math.h>

#define N_NODES 50000
#define N_EDGES 640000
#define NH (N_NODES * 128)
#define NB 196  // ceil(N_NODES / 256)

// ---------------- scratch (static device globals) ---------------------------
// INVARIANT: g_indeg and g_cursor are zero at the start of every kernel_launch
// call: zero-initialized at module load, and scan_bc re-zeros g_indeg after
// consuming it (g_cursor is zeroed by scan_bc before fill uses it) each run.
__device__ uint32_t g_hhb[NH / 2];    // Hs @ gcn_w (unscaled), bf16x2 packed
__device__ uint32_t g_Wc[4 * 16384];  // tf32 weights: gate i, c, o, gcn_w
__device__ int   g_indeg[N_NODES];
__device__ float g_dg[N_NODES];       // rsqrt(1 + indeg)
__device__ int   g_off[N_NODES + 1];
__device__ int   g_cursor[N_NODES];
__device__ int   g_csr[N_EDGES];
__device__ int   g_part[256];
// fused per-channel constants
__device__ float g_cb0[128], g_cb1[128], g_cb2[128], g_wc2[128];
__device__ float g_fa[128];
__device__ float g_fc;

// ---------------- helpers ----------------------------------------------------
__device__ __forceinline__ float tanhfast(float x) {
    float r; asm("tanh.approx.f32 %0, %1;" : "=f"(r) : "f"(x)); return r;
}
__device__ __forceinline__ float sigfast(float x) {
    return 0.5f * tanhfast(0.5f * x) + 0.5f;
}
__device__ __forceinline__ uint32_t to_tf32(float x) {
    uint32_t u; asm("cvt.rna.tf32.f32 %0, %1;" : "=r"(u) : "f"(x)); return u;
}
__device__ __forceinline__ uint32_t pack_bf16x2(float hi, float lo) {
    uint32_t u; asm("cvt.rn.bf16x2.f32 %0, %1, %2;" : "=r"(u) : "f"(hi), "f"(lo)); return u;
}
__device__ __forceinline__ float bf_lo(uint32_t u) { return __uint_as_float(u << 16); }
__device__ __forceinline__ float bf_hi(uint32_t u) { return __uint_as_float(u & 0xffff0000u); }
__device__ __forceinline__ void mma_tf32(float* d, const uint32_t* a, uint32_t b0, uint32_t b1) {
    asm volatile(
        "mma.sync.aligned.m16n8k8.row.col.f32.tf32.tf32.f32 "
        "{%0,%1,%2,%3}, {%4,%5,%6,%7}, {%8,%9}, {%0,%1,%2,%3};"
        : "+f"(d[0]), "+f"(d[1]), "+f"(d[2]), "+f"(d[3])
        : "r"(a[0]), "r"(a[1]), "r"(a[2]), "r"(a[3]), "r"(b0), "r"(b1));
}
__device__ __forceinline__ uint32_t smem_u32(const void* p) {
    uint32_t a;
    asm("{ .reg .u64 t; cvta.to.shared.u64 t, %1; cvt.u32.u64 %0, t; }" : "=r"(a) : "l"(p));
    return a;
}
__device__ __forceinline__ void cp_async16(uint32_t daddr, const void* saddr, int srcsz) {
    asm volatile("cp.async.cg.shared.global [%0], [%1], 16, %2;"
                 :: "r"(daddr), "l"(saddr), "r"(srcsz) : "memory");
}

// ---------------- prep: weights->tf32 + per-channel constants ----------------
__global__ void prep_all(const float* __restrict__ Wx, const float* __restrict__ gcn,
                         const float* __restrict__ theta_b, const float* __restrict__ b,
                         const float* __restrict__ w_c,
                         const float* __restrict__ gamma, const float* __restrict__ beta,
                         const float* __restrict__ mean, const float* __restrict__ var,
                         const float* __restrict__ lin_w, const float* __restrict__ lin_b) {
    if (blockIdx.x < 256) {
        int i = blockIdx.x * 256 + threadIdx.x;   // 0..65535
        int m = i >> 14, r = i & 16383;
        const float* S = (m == 0) ? Wx
                       : (m == 1) ? Wx + 2 * 16384
                       : (m == 2) ? Wx + 3 * 16384 : gcn;
        g_Wc[i] = to_tf32(S[r]);
        return;
    }
    int ch = threadIdx.x;
    if (ch >= 128) return;
    g_cb0[ch] = theta_b[ch] + b[ch];
    g_cb1[ch] = theta_b[256 + ch] + b[256 + ch];
    g_cb2[ch] = theta_b[384 + ch] + b[384 + ch];
    g_wc2[ch] = w_c[256 + ch];
    float sc = gamma[ch] * rsqrtf(var[ch] + 1e-5f);
    g_fa[ch] = sc * lin_w[ch];
    __shared__ float red[128];
    red[ch] = (beta[ch] - mean[ch] * sc) * lin_w[ch];
    __syncthreads();
    for (int o = 64; o > 0; o >>= 1) { if (ch < o) red[ch] += red[ch + o]; __syncthreads(); }
    if (ch == 0) g_fc = red[0] + lin_b[0];
}

__global__ void count_kernel(const int* __restrict__ dst) {
    int e = blockIdx.x * blockDim.x + threadIdx.x;
    if (e < N_EDGES) atomicAdd(&g_indeg[dst[e]], 1);
}

// ---- scan stage A: per-block partial sums ----
__global__ __launch_bounds__(256) void scan_a() {
    int i = blockIdx.x * 256 + threadIdx.x;
    int v = (i < N_NODES) ? g_indeg[i] : 0;
    int lane = threadIdx.x & 31, warp = threadIdx.x >> 5;
#pragma unroll
    for (int o = 16; o > 0; o >>= 1) v += __shfl_down_sync(0xffffffffu, v, o);
    __shared__ int ws[8];
    if (lane == 0) ws[warp] = v;
    __syncthreads();
    if (threadIdx.x == 0) {
        int s = 0;
#pragma unroll
        for (int w = 0; w < 8; w++) s += ws[w];
        g_part[blockIdx.x] = s;
    }
}
// ---- scan stage BC: re-scan partials + local scan; zero indeg after use ----
__global__ __launch_bounds__(256) void scan_bc() {
    int t = threadIdx.x, lane = t & 31, warp = t >> 5;
    __shared__ int s2[256];
    __shared__ int ws[8];
    {
        int v = (t < NB) ? g_part[t] : 0;
        int x = v;
#pragma unroll
        for (int o = 1; o < 32; o <<= 1) {
            int y = __shfl_up_sync(0xffffffffu, x, o);
            if (lane >= o) x += y;
        }
        if (lane == 31) ws[warp] = x;
        __syncthreads();
        if (warp == 0 && lane < 8) {
            int w = ws[lane];
#pragma unroll
            for (int o = 1; o < 8; o <<= 1) {
                int y = __shfl_up_sync(0xffu, w, o);
                if (lane >= o) w += y;
            }
            ws[lane] = w;
        }
        __syncthreads();
        s2[t] = x + (warp > 0 ? ws[warp - 1] : 0);
        __syncthreads();
    }
    int blockbase = (blockIdx.x == 0) ? 0 : s2[blockIdx.x - 1];
    __syncthreads();
    int i = blockIdx.x * 256 + t;
    int v = (i < N_NODES) ? g_indeg[i] : 0;
    int x = v;
#pragma unroll
    for (int o = 1; o < 32; o <<= 1) {
        int y = __shfl_up_sync(0xffffffffu, x, o);
        if (lane >= o) x += y;
    }
    if (lane == 31) ws[warp] = x;
    __syncthreads();
    if (warp == 0 && lane < 8) {
        int w = ws[lane];
#pragma unroll
        for (int o = 1; o < 8; o <<= 1) {
            int y = __shfl_up_sync(0xffu, w, o);
            if (lane >= o) w += y;
        }
        ws[lane] = w;
    }
    __syncthreads();
    if (i < N_NODES) {
        g_off[i] = x - v + (warp > 0 ? ws[warp - 1] : 0) + blockbase;
        g_dg[i] = rsqrtf(1.0f + (float)v);
        g_cursor[i] = 0;
        g_indeg[i] = 0;  // restore invariant for next replay
    }
    if (blockIdx.x == 0 && t == 0) g_off[N_NODES] = N_EDGES;
}

__global__ void fill_kernel(const int* __restrict__ src, const int* __restrict__ dst) {
    int e = blockIdx.x * blockDim.x + threadIdx.x;
    if (e >= N_EDGES) return;
    int d = dst[e];
    g_csr[g_off[d] + atomicAdd(&g_cursor[d], 1)] = src[e];
}

// ============================================================================
// Fully fused GEMM: gates (3x tf32 MMA) + LSTM -> Hs (smem) -> Hs@gcn_w
// -> bf16x2 hh.  256 threads, 8 warps (2m x 4n), warp tile 64x32.
// ============================================================================
__global__ __launch_bounds__(256, 1) void gemm_fused(
    const float* __restrict__ A, const uint32_t* __restrict__ W,
    uint32_t* __restrict__ out, int M)
{
    extern __shared__ uint32_t sm[];
    const int tid = threadIdx.x, lane = tid & 31;
    const int wid = tid >> 5, wm = wid >> 2, wn = wid & 3;
    const int q = lane >> 2, r = lane & 3;
    const int rowblk = blockIdx.x * 128;
    const uint32_t sbase = smem_u32(sm);

    float C[3][4][4][4];
#pragma unroll
    for (int g = 0; g < 3; g++)
#pragma unroll
        for (int i = 0; i < 4; i++)
#pragma unroll
            for (int j = 0; j < 4; j++)
#pragma unroll
                for (int k = 0; k < 4; k++) C[g][i][j][k] = 0.0f;

    // ================= phase 1: z = x @ W_gate for 3 gates =================
#pragma unroll
    for (int chunk = 0; chunk < 2; chunk++) {
        const int k0 = chunk * 64;
        if (chunk) __syncthreads();
#pragma unroll
        for (int g = 0; g < 3; g++) {
#pragma unroll
            for (int t = 0; t < 8; t++) {
                int i = tid + t * 256;
                int row = i >> 5, j = i & 31;
                cp_async16(sbase + (8704 * (1 + g) + row * 136 + j * 4) * 4,
                           W + (size_t)g * 16384 + (size_t)(k0 + row) * 128 + j * 4, 16);
            }
        }
        asm volatile("cp.async.commit_group;" ::: "memory");
#pragma unroll
        for (int t = 0; t < 8; t++) {
            int i = tid + t * 256;
            int row = i >> 4, j = i & 15;
            int gr = rowblk + row;
            float4 v = make_float4(0.f, 0.f, 0.f, 0.f);
            if (gr < M) v = *(const float4*)(A + (size_t)gr * 128 + k0 + j * 4);
            uint4 w;
            w.x = to_tf32(v.x); w.y = to_tf32(v.y);
            w.z = to_tf32(v.z); w.w = to_tf32(v.w);
            *(uint4*)(&sm[row * 68 + j * 4]) = w;   // 16B-aligned (272*row+16*j)
        }
        asm volatile("cp.async.wait_group 0;" ::: "memory");
        __syncthreads();

#pragma unroll
        for (int ks = 0; ks < 8; ks++) {
            const int kb = ks * 8;
            uint32_t a[4][4];
#pragma unroll
            for (int ma = 0; ma < 4; ma++) {
                int m = wm * 64 + ma * 16 + q;
                const uint32_t* ap = &sm[m * 68 + kb + r];
                a[ma][0] = ap[0];
                a[ma][2] = ap[4];
                a[ma][1] = ap[8 * 68];
                a[ma][3] = ap[8 * 68 + 4];
            }
#pragma unroll
            for (int g = 0; g < 3; g++) {
                const uint32_t* bs = sm + 8704 * (1 + g);
#pragma unroll
                for (int na = 0; na < 4; na++) {
                    int n = wn * 32 + na * 8 + q;
                    const uint32_t* bp = &bs[(kb + r) * 136 + n];
                    uint32_t b0 = bp[0], b1 = bp[4 * 136];
#pragma unroll
                    for (int ma = 0; ma < 4; ma++) mma_tf32(C[g][ma][na], a[ma], b0, b1);
                }
            }
        }
    }
    __syncthreads();  // all reads of A/B done before overwrite

    // gcn_w loads into bufs 2,3 (overlap LSTM epilogue math)
#pragma unroll
    for (int t = 0; t < 16; t++) {
        int i = tid + t * 256;
        int chunk = i >> 11;
        int rj = i & 2047;
        int row = rj >> 5, j = rj & 31;
        cp_async16(sbase + (8704 * (2 + chunk) + row * 136 + j * 4) * 4,
                   W + 3 * 16384 + (size_t)(chunk * 64 + row) * 128 + j * 4, 16);
    }
    asm volatile("cp.async.commit_group;" ::: "memory");

    // ============ LSTM epilogue -> Hs (tf32 bits) into smem bufs 0,1 ========
#pragma unroll
    for (int ma = 0; ma < 4; ma++) {
#pragma unroll
        for (int half = 0; half < 2; half++) {
            int lrow = wm * 64 + ma * 16 + q + half * 8;
#pragma unroll
            for (int na = 0; na < 4; na++) {
                int ch = wn * 32 + na * 8 + 2 * r;
                uint2 h2;
                {
                    int c = ch;
                    float zi = C[0][ma][na][half * 2] + g_cb0[c];
                    float zc = C[1][ma][na][half * 2] + g_cb1[c];
                    float zo = C[2][ma][na][half * 2] + g_cb2[c];
                    float I = sigfast(zi);
                    float T = tanhfast(zc);
                    float Cs = I * T;
                    float O = sigfast(zo + g_wc2[c] * Cs);
                    h2.x = to_tf32(O * tanhfast(Cs));
                }
                {
                    int c = ch + 1;
                    float zi = C[0][ma][na][half * 2 + 1] + g_cb0[c];
                    float zc = C[1][ma][na][half * 2 + 1] + g_cb1[c];
                    float zo = C[2][ma][na][half * 2 + 1] + g_cb2[c];
                    float I = sigfast(zi);
                    float T = tanhfast(zc);
                    float Cs = I * T;
                    float O = sigfast(zo + g_wc2[c] * Cs);
                    h2.y = to_tf32(O * tanhfast(Cs));
                }
                int cchunk = ch >> 6, col = ch & 63;
                *(uint2*)(&sm[cchunk * 8704 + lrow * 68 + col]) = h2;  // 8B-aligned
            }
        }
    }
    asm volatile("cp.async.wait_group 0;" ::: "memory");
    __syncthreads();

    // ================= phase 2: hh = Hs @ gcn_w =============================
    float D[4][4][4];
#pragma unroll
    for (int i = 0; i < 4; i++)
#pragma unroll
        for (int j = 0; j < 4; j++)
#pragma unroll
            for (int k = 0; k < 4; k++) D[i][j][k] = 0.0f;

#pragma unroll
    for (int chunk = 0; chunk < 2; chunk++) {
        const uint32_t* as = sm + chunk * 8704;
        const uint32_t* bs = sm + (2 + chunk) * 8704;
#pragma unroll
        for (int ks = 0; ks < 8; ks++) {
            const int kb = ks * 8;
            uint32_t a[4][4];
#pragma unroll
            for (int ma = 0; ma < 4; ma++) {
                int m = wm * 64 + ma * 16 + q;
                const uint32_t* ap = &as[m * 68 + kb + r];
                a[ma][0] = ap[0];
                a[ma][2] = ap[4];
                a[ma][1] = ap[8 * 68];
                a[ma][3] = ap[8 * 68 + 4];
            }
#pragma unroll
            for (int na = 0; na < 4; na++) {
                int n = wn * 32 + na * 8 + q;
                const uint32_t* bp = &bs[(kb + r) * 136 + n];
                uint32_t b0 = bp[0], b1 = bp[4 * 136];
#pragma unroll
                for (int ma = 0; ma < 4; ma++) mma_tf32(D[ma][na], a[ma], b0, b1);
            }
        }
    }

    // ---- epilogue 2: write hh as bf16x2 ----
#pragma unroll
    for (int ma = 0; ma < 4; ma++) {
#pragma unroll
        for (int half = 0; half < 2; half++) {
            int row = rowblk + wm * 64 + ma * 16 + q + half * 8;
            if (row >= M) continue;
#pragma unroll
            for (int na = 0; na < 4; na++) {
                int ch = wn * 32 + na * 8 + 2 * r;
                out[(size_t)row * 64 + (ch >> 1)] =
                    pack_bf16x2(D[ma][na][half * 2 + 1], D[ma][na][half * 2]);
            }
        }
    }
}

// ============================================================================
// gather + finalize: warp per node, bf16 hh; cnt from CSR offsets
// ============================================================================
__global__ __launch_bounds__(256) void gather_finalize(const float* __restrict__ gcn_b,
                                                       float* __restrict__ out)
{
    int node = (blockIdx.x * blockDim.x + threadIdx.x) >> 5;
    int lane = threadIdx.x & 31;
    if (node >= N_NODES) return;
    int base = g_off[node];
    int cnt = g_off[node + 1] - base;
    float dgi = g_dg[node];

    const uint2* hh2 = (const uint2*)g_hhb;
    uint2 hv = hh2[(size_t)node * 32 + lane];
    float a0 = dgi * bf_lo(hv.x), a1 = dgi * bf_hi(hv.x);
    float a2 = dgi * bf_lo(hv.y), a3 = dgi * bf_hi(hv.y);

    for (int e0 = 0; e0 < cnt; e0 += 32) {
        int myidx = (e0 + lane < cnt) ? g_csr[base + e0 + lane] : 0;
        int lim = min(32, cnt - e0);
        int t = 0;
        for (; t + 4 <= lim; t += 4) {
            int s0 = __shfl_sync(0xffffffffu, myidx, t);
            int s1 = __shfl_sync(0xffffffffu, myidx, t + 1);
            int s2 = __shfl_sync(0xffffffffu, myidx, t + 2);
            int s3 = __shfl_sync(0xffffffffu, myidx, t + 3);
            float d0 = __ldg(g_dg + s0);
            float d1 = __ldg(g_dg + s1);
            float d2 = __ldg(g_dg + s2);
            float d3 = __ldg(g_dg + s3);
            uint2 v0 = __ldg(hh2 + (size_t)s0 * 32 + lane);
            uint2 v1 = __ldg(hh2 + (size_t)s1 * 32 + lane);
            uint2 v2 = __ldg(hh2 + (size_t)s2 * 32 + lane);
            uint2 v3 = __ldg(hh2 + (size_t)s3 * 32 + lane);
            a0 = fmaf(d0, bf_lo(v0.x), a0); a1 = fmaf(d0, bf_hi(v0.x), a1);
            a2 = fmaf(d0, bf_lo(v0.y), a2); a3 = fmaf(d0, bf_hi(v0.y), a3);
            a0 = fmaf(d1, bf_lo(v1.x), a0); a1 = fmaf(d1, bf_hi(v1.x), a1);
            a2 = fmaf(d1, bf_lo(v1.y), a2); a3 = fmaf(d1, bf_hi(v1.y), a3);
            a0 = fmaf(d2, bf_lo(v2.x), a0); a1 = fmaf(d2, bf_hi(v2.x), a1);
            a2 = fmaf(d2, bf_lo(v2.y), a2); a3 = fmaf(d2, bf_hi(v2.y), a3);
            a0 = fmaf(d3, bf_lo(v3.x), a0); a1 = fmaf(d3, bf_hi(v3.x), a1);
            a2 = fmaf(d3, bf_lo(v3.y), a2); a3 = fmaf(d3, bf_hi(v3.y), a3);
        }
        for (; t < lim; t++) {
            int s = __shfl_sync(0xffffffffu, myidx, t);
            float ds = __ldg(g_dg + s);
            uint2 v = __ldg(hh2 + (size_t)s * 32 + lane);
            a0 = fmaf(ds, bf_lo(v.x), a0);
            a1 = fmaf(ds, bf_hi(v.x), a1);
            a2 = fmaf(ds, bf_lo(v.y), a2);
            a3 = fmaf(ds, bf_hi(v.y), a3);
        }
    }

    float4 gb = ((const float4*)gcn_b)[lane];
    float4 fa = ((const float4*)g_fa)[lane];
    float sum = fmaxf(dgi * a0 + gb.x, 0.0f) * fa.x
              + fmaxf(dgi * a1 + gb.y, 0.0f) * fa.y
              + fmaxf(dgi * a2 + gb.z, 0.0f) * fa.z
              + fmaxf(dgi * a3 + gb.w, 0.0f) * fa.w;
#pragma unroll
    for (int o = 16; o > 0; o >>= 1) sum += __shfl_down_sync(0xffffffffu, sum, o);
    if (lane == 0) out[node] = sum + g_fc;
}

// ============================================================================
// launch. Enqueue order puts gemm_fused 4th so ncu (-s 5 after 2 harness
// kernels) captures it. Stream deps: main = prep -> gemm -> gather;
// s1 = count -> scan_a -> scan_bc -> fill (independent of prep).
// ============================================================================
extern "C" void kernel_launch(void* const* d_in, const int* in_sizes, int n_in,
                              void* d_out, int out_size)
{
    const float* x        = (const float*)d_in[0];
    const int*   ei       = (const int*)  d_in[1];
    const float* W_x      = (const float*)d_in[3];
    const float* w_c      = (const float*)d_in[4];
    const float* b        = (const float*)d_in[5];
    const float* theta_b  = (const float*)d_in[7];
    const float* gcn_w    = (const float*)d_in[8];
    const float* gcn_b    = (const float*)d_in[9];
    const float* bn_gamma = (const float*)d_in[10];
    const float* bn_beta  = (const float*)d_in[11];
    const float* bn_mean  = (const float*)d_in[12];
    const float* bn_var   = (const float*)d_in[13];
    const float* lin_w    = (const float*)d_in[14];
    const float* lin_b    = (const float*)d_in[15];
    float* out = (float*)d_out;

    const int* src = ei;
    const int* dst = ei + N_EDGES;

    const int SMF = 8704 * 4 * 4;  // 139264 B

    static cudaStream_t s1 = nullptr;
    static cudaEvent_t evRoot, evCsr;
    if (!s1) {
        cudaStreamCreateWithFlags(&s1, cudaStreamNonBlocking);
        cudaEventCreateWithFlags(&evRoot, cudaEventDisableTiming);
        cudaEventCreateWithFlags(&evCsr,  cudaEventDisableTiming);
        cudaFuncSetAttribute((const void*)gemm_fused,
                             cudaFuncAttributeMaxDynamicSharedMemorySize, SMF);
    }

    uint32_t *hhp, *wcp;
    cudaGetSymbolAddress((void**)&hhp, g_hhb);
    cudaGetSymbolAddress((void**)&wcp, g_Wc);

    // fork s1 from main at graph root
    cudaEventRecord(evRoot, 0);
    cudaStreamWaitEvent(s1, evRoot, 0);

    // enqueue order chosen so gemm_fused is the 4th kernel launched
    prep_all<<<257, 256>>>(W_x, gcn_w, theta_b, b, w_c,                 // #1 (main)
                           bn_gamma, bn_beta, bn_mean, bn_var, lin_w, lin_b);
    count_kernel<<<(N_EDGES + 255) / 256, 256, 0, s1>>>(dst);           // #2 (s1)
    scan_a<<<NB, 256, 0, s1>>>();                                       // #3 (s1)
    gemm_fused<<<(N_NODES + 127) / 128, 256, SMF>>>(x, wcp, hhp, N_NODES); // #4 (main)
    scan_bc<<<NB, 256, 0, s1>>>();                                      // #5 (s1)
    fill_kernel<<<(N_EDGES + 255) / 256, 256, 0, s1>>>(src, dst);       // #6 (s1)
    cudaEventRecord(evCsr, s1);

    // join: gather needs gemm (stream order) + CSR (event)
    cudaStreamWaitEvent(0, evCsr, 0);
    gather_finalize<<<(N_NODES * 32 + 255) / 256, 256>>>(gcn_b, out);   // #7 (main)
}